// round 1
// baseline (speedup 1.0000x reference)
#include <cuda_runtime.h>
#include <math.h>

#define B_   2
#define S_   2048
#define H_   4096
#define NH_  32
#define NKV_ 8
#define HD_  128
#define TOK  (B_*S_)        // 4096

// ---------------- scratch (static device globals; no allocation) ----------
__device__ float g_Q[(size_t)B_*NH_*S_*HD_];   // [B,NH,S,D]   64MB
__device__ float g_K[(size_t)B_*NKV_*S_*HD_];  // [B,NKV,S,D]  16MB
__device__ float g_V[(size_t)B_*NKV_*S_*HD_];  // 16MB
__device__ float g_O[(size_t)TOK*H_];          // [T, NH*D]    64MB
__device__ float g_cos[S_*64];
__device__ float g_sin[S_*64];

// ---------------- packed f32x2 helpers ------------------------------------
__device__ __forceinline__ unsigned long long pack2(float x, float y){
    unsigned long long r;
    asm("mov.b64 %0, {%1, %2};" : "=l"(r) : "f"(x), "f"(y));
    return r;
}
__device__ __forceinline__ float2 unpack2(unsigned long long v){
    float2 r;
    asm("mov.b64 {%0, %1}, %2;" : "=f"(r.x), "=f"(r.y) : "l"(v));
    return r;
}
#define FMA2(d, a, b) asm("fma.rn.f32x2 %0, %1, %2, %0;" : "+l"(d) : "l"(a), "l"(b))
#define MUL2(d, a)    asm("mul.rn.f32x2 %0, %0, %1;"     : "+l"(d) : "l"(a))

// ---------------- rope tables ----------------------------------------------
__global__ void rope_tables_kernel(){
    int idx = blockIdx.x * blockDim.x + threadIdx.x;
    if (idx >= S_*64) return;
    int s = idx >> 6, j = idx & 63;
    double inv = pow(500000.0, -((double)j)/64.0);
    float ang = (float)s * (float)inv;            // f32 product (matches ref rounding)
    g_cos[idx] = (float)cos((double)ang);
    g_sin[idx] = (float)sin((double)ang);
}

// ---------------- generic NT GEMM: C[M,N] = A[M,K] * B[N,K]^T --------------
// mode 0: store C row-major with ld=H_.  mode 1: head-major store into g_Q/g_K/g_V.
__global__ __launch_bounds__(256, 2)
void gemm_nt_kernel(const float* __restrict__ A, const float* __restrict__ Bm,
                    float* __restrict__ Cout, int K, int mode, int n_heads,
                    int dest, int srcO)
{
    __shared__ float As[16][132];
    __shared__ float Bs[16][132];

    const float* Ap = srcO ? (const float*)g_O : A;
    float* Cp;
    if      (dest == 0) Cp = g_Q;
    else if (dest == 1) Cp = g_K;
    else if (dest == 2) Cp = g_V;
    else                Cp = Cout;

    const int tid = threadIdx.x;
    const int tx  = tid & 15, ty = tid >> 4;
    const int M0  = blockIdx.y << 7, N0 = blockIdx.x << 7;
    const int t0  = tid, t1 = tid + 256;

    unsigned long long acc[8][4];
    #pragma unroll
    for (int i = 0; i < 8; ++i)
        #pragma unroll
        for (int j = 0; j < 4; ++j) acc[i][j] = 0ULL;

    const int r0 = t0 >> 2, c0 = (t0 & 3) << 2;
    const int r1 = t1 >> 2, c1 = (t1 & 3) << 2;

    float4 ra0, ra1, rb0, rb1;
    // prologue load
    ra0 = *(const float4*)(Ap + (size_t)(M0 + r0)*K + c0);
    ra1 = *(const float4*)(Ap + (size_t)(M0 + r1)*K + c1);
    rb0 = *(const float4*)(Bm + (size_t)(N0 + r0)*K + c0);
    rb1 = *(const float4*)(Bm + (size_t)(N0 + r1)*K + c1);

    const int KT = K >> 4;
    for (int kt = 0; kt < KT; ++kt){
        // commit registers -> smem (transposed)
        As[c0+0][r0] = ra0.x; As[c0+1][r0] = ra0.y; As[c0+2][r0] = ra0.z; As[c0+3][r0] = ra0.w;
        As[c1+0][r1] = ra1.x; As[c1+1][r1] = ra1.y; As[c1+2][r1] = ra1.z; As[c1+3][r1] = ra1.w;
        Bs[c0+0][r0] = rb0.x; Bs[c0+1][r0] = rb0.y; Bs[c0+2][r0] = rb0.z; Bs[c0+3][r0] = rb0.w;
        Bs[c1+0][r1] = rb1.x; Bs[c1+1][r1] = rb1.y; Bs[c1+2][r1] = rb1.z; Bs[c1+3][r1] = rb1.w;
        __syncthreads();

        if (kt + 1 < KT){
            int kc = (kt + 1) << 4;
            ra0 = *(const float4*)(Ap + (size_t)(M0 + r0)*K + kc + c0);
            ra1 = *(const float4*)(Ap + (size_t)(M0 + r1)*K + kc + c1);
            rb0 = *(const float4*)(Bm + (size_t)(N0 + r0)*K + kc + c0);
            rb1 = *(const float4*)(Bm + (size_t)(N0 + r1)*K + kc + c1);
        }

        #pragma unroll
        for (int kk = 0; kk < 16; ++kk){
            float4 a0 = *(const float4*)(&As[kk][ty << 3]);
            float4 a1 = *(const float4*)(&As[kk][(ty << 3) + 4]);
            unsigned long long bv[4];
            #pragma unroll
            for (int j = 0; j < 4; ++j)
                bv[j] = *(const unsigned long long*)(&Bs[kk][(tx << 3) + (j << 1)]);
            float av[8] = {a0.x, a0.y, a0.z, a0.w, a1.x, a1.y, a1.z, a1.w};
            #pragma unroll
            for (int i = 0; i < 8; ++i){
                unsigned long long ad = pack2(av[i], av[i]);
                #pragma unroll
                for (int j = 0; j < 4; ++j) FMA2(acc[i][j], ad, bv[j]);
            }
        }
        __syncthreads();
    }

    // epilogue
    #pragma unroll
    for (int i = 0; i < 8; ++i){
        int r = M0 + (ty << 3) + i;                 // global row (token)
        #pragma unroll
        for (int j = 0; j < 4; ++j){
            float2 v = unpack2(acc[i][j]);
            int c = N0 + (tx << 3) + (j << 1);      // global col
            if (mode == 0){
                *(float2*)(Cp + (size_t)r * H_ + c) = v;
            } else {
                int b = r >> 11, s = r & (S_ - 1);
                int h = c >> 7,  d = c & (HD_ - 1);
                size_t idx = (((size_t)b * n_heads + h) * S_ + s) * HD_ + d;
                *(float2*)(Cp + idx) = v;
            }
        }
    }
}

// ---------------- RoPE (in-place) ------------------------------------------
__global__ void rope_apply_kernel(int which, int rows){
    int idx = blockIdx.x * blockDim.x + threadIdx.x;
    if (idx >= (rows << 6)) return;
    float* X = which ? g_K : g_Q;
    int r = idx >> 6, j = idx & 63;
    int s = r & (S_ - 1);
    float c  = g_cos[(s << 6) + j];
    float sn = g_sin[(s << 6) + j];
    float* p = X + ((size_t)r << 7);
    float x1 = p[j], x2 = p[j + 64];
    p[j]      = x1 * c - x2 * sn;
    p[j + 64] = x2 * c + x1 * sn;
}

// ---------------- flash attention (non-causal, fp32) ------------------------
// grid: (S/64, NH, B); 256 threads; smem 119808B
#define QK_LD 68
#define ATT_SMEM ((128*QK_LD + 128*QK_LD + 64*128 + 64*QK_LD) * 4)

__global__ __launch_bounds__(256, 1)
void attn_kernel(){
    extern __shared__ float sm[];
    float* Qs = sm;                      // [128][68] d-major (transposed), pre-scaled
    float* Ks = Qs + 128*QK_LD;          // [128][68]
    float* Vs = Ks + 128*QK_LD;          // [64][128]
    float* Ps = Vs + 64*128;             // [64][68]  (k-major)

    const int tid = threadIdx.x;
    const int tx  = tid & 15, ty = tid >> 4;
    const int qb  = blockIdx.x;
    const int h   = blockIdx.y;
    const int b   = blockIdx.z;
    const int g   = h >> 2;

    const float* Qg = g_Q + (((size_t)b*NH_  + h)*S_ + (size_t)qb*64) * HD_;
    const float* Kg = g_K + (((size_t)b*NKV_ + g)*S_) * HD_;
    const float* Vg = g_V + (((size_t)b*NKV_ + g)*S_) * HD_;

    const float qscale = 0.08838834764831845f;  // 1/sqrt(128)
    #pragma unroll
    for (int t = tid; t < 64*32; t += 256){
        int row = t >> 5, dg = (t & 31) << 2;
        float4 v = *(const float4*)(Qg + (size_t)row*HD_ + dg);
        Qs[(dg+0)*QK_LD + row] = v.x * qscale;
        Qs[(dg+1)*QK_LD + row] = v.y * qscale;
        Qs[(dg+2)*QK_LD + row] = v.z * qscale;
        Qs[(dg+3)*QK_LD + row] = v.w * qscale;
    }

    float m_i[4], l_i[4];
    unsigned long long o2[4][4];
    #pragma unroll
    for (int qi = 0; qi < 4; ++qi){
        m_i[qi] = -INFINITY; l_i[qi] = 0.f;
        #pragma unroll
        for (int j = 0; j < 4; ++j) o2[qi][j] = 0ULL;
    }

    for (int kb = 0; kb < S_/64; ++kb){
        const float* Kt = Kg + (size_t)kb*64*HD_;
        const float* Vt = Vg + (size_t)kb*64*HD_;
        __syncthreads();   // previous PV done before overwriting K/V/Ps
        #pragma unroll
        for (int t = tid; t < 64*32; t += 256){
            int row = t >> 5, dg = (t & 31) << 2;
            float4 kv = *(const float4*)(Kt + (size_t)row*HD_ + dg);
            Ks[(dg+0)*QK_LD + row] = kv.x;
            Ks[(dg+1)*QK_LD + row] = kv.y;
            Ks[(dg+2)*QK_LD + row] = kv.z;
            Ks[(dg+3)*QK_LD + row] = kv.w;
            *(float4*)(Vs + (size_t)row*HD_ + dg) = *(const float4*)(Vt + (size_t)row*HD_ + dg);
        }
        __syncthreads();

        // ---- S = (Q*scale) K^T : each thread 4 q-rows x 4 k-cols ----
        unsigned long long s2[4][2];
        #pragma unroll
        for (int qi = 0; qi < 4; ++qi){ s2[qi][0] = 0ULL; s2[qi][1] = 0ULL; }
        #pragma unroll 4
        for (int d = 0; d < 128; ++d){
            const float* qrow = Qs + d*QK_LD;
            const float* krow = Ks + d*QK_LD;
            float4 q = *(const float4*)(qrow + (ty << 2));
            unsigned long long k0 = *(const unsigned long long*)(krow + (tx << 2));
            unsigned long long k1 = *(const unsigned long long*)(krow + (tx << 2) + 2);
            float qv[4] = {q.x, q.y, q.z, q.w};
            #pragma unroll
            for (int qi = 0; qi < 4; ++qi){
                unsigned long long qd = pack2(qv[qi], qv[qi]);
                FMA2(s2[qi][0], qd, k0);
                FMA2(s2[qi][1], qd, k1);
            }
        }

        // ---- online softmax ----
        #pragma unroll
        for (int qi = 0; qi < 4; ++qi){
            float2 sa = unpack2(s2[qi][0]);
            float2 sb = unpack2(s2[qi][1]);
            float sv[4] = {sa.x, sa.y, sb.x, sb.y};
            float mb = fmaxf(fmaxf(sv[0], sv[1]), fmaxf(sv[2], sv[3]));
            #pragma unroll
            for (int off = 8; off; off >>= 1)
                mb = fmaxf(mb, __shfl_xor_sync(0xffffffffu, mb, off));
            float mn = fmaxf(m_i[qi], mb);
            float corr = __expf(m_i[qi] - mn);
            m_i[qi] = mn;
            float ls = 0.f;
            #pragma unroll
            for (int kj = 0; kj < 4; ++kj){
                float p = __expf(sv[kj] - mn);
                ls += p;
                Ps[((tx << 2) + kj)*QK_LD + (ty << 2) + qi] = p;
            }
            #pragma unroll
            for (int off = 8; off; off >>= 1)
                ls += __shfl_xor_sync(0xffffffffu, ls, off);
            l_i[qi] = l_i[qi] * corr + ls;
            unsigned long long c2 = pack2(corr, corr);
            #pragma unroll
            for (int j = 0; j < 4; ++j) MUL2(o2[qi][j], c2);
        }
        __syncthreads();

        // ---- O += P V : thread owns 4 q-rows x d-cols {2tx, 2tx+1} + 32*j ----
        #pragma unroll 2
        for (int k = 0; k < 64; ++k){
            float4 pv = *(const float4*)(Ps + k*QK_LD + (ty << 2));
            const float* vrow = Vs + (k << 7);
            unsigned long long v0 = *(const unsigned long long*)(vrow + (tx << 1));
            unsigned long long v1 = *(const unsigned long long*)(vrow + (tx << 1) + 32);
            unsigned long long v2 = *(const unsigned long long*)(vrow + (tx << 1) + 64);
            unsigned long long v3 = *(const unsigned long long*)(vrow + (tx << 1) + 96);
            float pf[4] = {pv.x, pv.y, pv.z, pv.w};
            #pragma unroll
            for (int qi = 0; qi < 4; ++qi){
                unsigned long long pd = pack2(pf[qi], pf[qi]);
                FMA2(o2[qi][0], pd, v0);
                FMA2(o2[qi][1], pd, v1);
                FMA2(o2[qi][2], pd, v2);
                FMA2(o2[qi][3], pd, v3);
            }
        }
    }

    // ---- epilogue: normalize, write [b, s, h*128 + d] ----
    float* Og = g_O + ((size_t)b*S_ + (size_t)qb*64) * H_ + (size_t)h*HD_;
    #pragma unroll
    for (int qi = 0; qi < 4; ++qi){
        float inv = 1.0f / l_i[qi];
        int row = (ty << 2) + qi;
        #pragma unroll
        for (int j = 0; j < 4; ++j){
            float2 v = unpack2(o2[qi][j]);
            v.x *= inv; v.y *= inv;
            int d = (tx << 1) + (j << 5);
            *(float2*)(Og + (size_t)row*H_ + d) = v;
        }
    }
}

// ---------------- launch ----------------------------------------------------
extern "C" void kernel_launch(void* const* d_in, const int* in_sizes, int n_in,
                              void* d_out, int out_size)
{
    const float* hs = (const float*)d_in[0];
    const float* Wq = (const float*)d_in[1];
    const float* Wk = (const float*)d_in[2];
    const float* Wv = (const float*)d_in[3];
    const float* Wo = (const float*)d_in[4];
    float* out = (float*)d_out;

    rope_tables_kernel<<<(S_*64 + 255)/256, 256>>>();

    // Q, K, V projections (head-major store)
    gemm_nt_kernel<<<dim3((NH_*HD_)/128,  TOK/128), 256>>>(hs, Wq, nullptr, H_, 1, NH_,  0, 0);
    gemm_nt_kernel<<<dim3((NKV_*HD_)/128, TOK/128), 256>>>(hs, Wk, nullptr, H_, 1, NKV_, 1, 0);
    gemm_nt_kernel<<<dim3((NKV_*HD_)/128, TOK/128), 256>>>(hs, Wv, nullptr, H_, 1, NKV_, 2, 0);

    // RoPE in place on Q and K
    rope_apply_kernel<<<(B_*NH_*S_*64)/256,  256>>>(0, B_*NH_*S_);
    rope_apply_kernel<<<(B_*NKV_*S_*64)/256, 256>>>(1, B_*NKV_*S_);

    // attention
    cudaFuncSetAttribute(attn_kernel, cudaFuncAttributeMaxDynamicSharedMemorySize, ATT_SMEM);
    attn_kernel<<<dim3(S_/64, NH_, B_), 256, ATT_SMEM>>>();

    // output projection -> d_out
    gemm_nt_kernel<<<dim3(H_/128, TOK/128), 256>>>(nullptr, Wo, out, H_, 0, 0, 3, 1);
}

// round 3
// speedup vs baseline: 1.5040x; 1.5040x over previous
#include <cuda_runtime.h>
#include <cuda_bf16.h>
#include <math.h>
#include <stdint.h>

#define B_   2
#define S_   2048
#define H_   4096
#define NH_  32
#define NKV_ 8
#define HD_  128
#define TOK  (B_*S_)        // 4096

// ---------------- scratch (static device globals; no allocation) ----------
__device__ float g_Q[(size_t)B_*NH_*S_*HD_];
__device__ float g_K[(size_t)B_*NKV_*S_*HD_];
__device__ float g_V[(size_t)B_*NKV_*S_*HD_];
__device__ float g_cos[S_*64];
__device__ float g_sin[S_*64];

// bf16 hi/lo split buffers
__device__ __nv_bfloat16 g_hsH[(size_t)TOK*H_], g_hsL[(size_t)TOK*H_];
__device__ __nv_bfloat16 g_WqH[(size_t)NH_*HD_*H_],  g_WqL[(size_t)NH_*HD_*H_];
__device__ __nv_bfloat16 g_WkH[(size_t)NKV_*HD_*H_], g_WkL[(size_t)NKV_*HD_*H_];
__device__ __nv_bfloat16 g_WvH[(size_t)NKV_*HD_*H_], g_WvL[(size_t)NKV_*HD_*H_];
__device__ __nv_bfloat16 g_WoH[(size_t)H_*H_],       g_WoL[(size_t)H_*H_];
__device__ __nv_bfloat16 g_OH[(size_t)TOK*H_],       g_OL[(size_t)TOK*H_];

// ---------------- helpers ----------------------------------------------------
__device__ __forceinline__ uint32_t smem_to_u32(const void* p){
    uint32_t a;
    asm("{ .reg .u64 t; cvta.to.shared.u64 t, %1; cvt.u32.u64 %0, t; }" : "=r"(a) : "l"(p));
    return a;
}
#define CP_ASYNC16(dst, src) \
    asm volatile("cp.async.cg.shared.global [%0], [%1], 16;" :: "r"(dst), "l"(src))
#define CP_COMMIT() asm volatile("cp.async.commit_group;" ::: "memory")
#define CP_WAIT1()  asm volatile("cp.async.wait_group 1;" ::: "memory")

#define LDSM_X4(r, addr) \
    asm volatile("ldmatrix.sync.aligned.m8n8.x4.shared.b16 {%0,%1,%2,%3}, [%4];" \
        : "=r"((r)[0]),"=r"((r)[1]),"=r"((r)[2]),"=r"((r)[3]) : "r"(addr))

#define MMA_BF16(c, a, b0, b1) \
    asm volatile("mma.sync.aligned.m16n8k16.row.col.f32.bf16.bf16.f32 " \
        "{%0,%1,%2,%3},{%4,%5,%6,%7},{%8,%9},{%0,%1,%2,%3};" \
        : "+f"((c)[0]),"+f"((c)[1]),"+f"((c)[2]),"+f"((c)[3]) \
        : "r"((a)[0]),"r"((a)[1]),"r"((a)[2]),"r"((a)[3]), "r"(b0),"r"(b1))

// packed f32x2 (attention)
__device__ __forceinline__ unsigned long long pack2(float x, float y){
    unsigned long long r;
    asm("mov.b64 %0, {%1, %2};" : "=l"(r) : "f"(x), "f"(y));
    return r;
}
__device__ __forceinline__ float2 unpack2(unsigned long long v){
    float2 r;
    asm("mov.b64 {%0, %1}, %2;" : "=f"(r.x), "=f"(r.y) : "l"(v));
    return r;
}
#define FMA2(d, a, b) asm("fma.rn.f32x2 %0, %1, %2, %0;" : "+l"(d) : "l"(a), "l"(b))
#define MUL2(d, a)    asm("mul.rn.f32x2 %0, %0, %1;"     : "+l"(d) : "l"(a))

// ---------------- rope tables ----------------------------------------------
__global__ void rope_tables_kernel(){
    int idx = blockIdx.x * blockDim.x + threadIdx.x;
    if (idx >= S_*64) return;
    int s = idx >> 6, j = idx & 63;
    double inv = pow(500000.0, -((double)j)/64.0);
    float ang = (float)s * (float)inv;
    g_cos[idx] = (float)cos((double)ang);
    g_sin[idx] = (float)sin((double)ang);
}

// ---------------- fp32 -> bf16 hi/lo split ----------------------------------
__global__ void split_kernel(const float* __restrict__ src, int n, int dsel){
    __nv_bfloat16 *dH, *dL;
    switch (dsel){
        case 0: dH = g_hsH; dL = g_hsL; break;
        case 1: dH = g_WqH; dL = g_WqL; break;
        case 2: dH = g_WkH; dL = g_WkL; break;
        case 3: dH = g_WvH; dL = g_WvL; break;
        default:dH = g_WoH; dL = g_WoL; break;
    }
    int i = (blockIdx.x * blockDim.x + threadIdx.x) << 2;
    if (i >= n) return;
    float4 v = *(const float4*)(src + i);
    __nv_bfloat16 h0 = __float2bfloat16(v.x), h1 = __float2bfloat16(v.y);
    __nv_bfloat16 h2 = __float2bfloat16(v.z), h3 = __float2bfloat16(v.w);
    __nv_bfloat16 l0 = __float2bfloat16(v.x - __bfloat162float(h0));
    __nv_bfloat16 l1 = __float2bfloat16(v.y - __bfloat162float(h1));
    __nv_bfloat16 l2 = __float2bfloat16(v.z - __bfloat162float(h2));
    __nv_bfloat16 l3 = __float2bfloat16(v.w - __bfloat162float(h3));
    __nv_bfloat162 a, b, c, d;
    a.x = h0; a.y = h1; b.x = h2; b.y = h3;
    c.x = l0; c.y = l1; d.x = l2; d.y = l3;
    *(__nv_bfloat162*)(dH + i)     = a;
    *(__nv_bfloat162*)(dH + i + 2) = b;
    *(__nv_bfloat162*)(dL + i)     = c;
    *(__nv_bfloat162*)(dL + i + 2) = d;
}

// ---------------- HMMA GEMM: C[M,N] = A[M,K]*B[N,K]^T, bf16 3-pass split ----
// BM=128 BN=128 BK=32; 8 warps (4x2); cp.async 3-stage; padded rows (80B).
#define BK_      32
#define ROWB     80                     // bytes per smem row (32 bf16 + 8 pad)
#define MATB     (128*ROWB)             // 10240 B per matrix
#define STGB     (4*MATB)               // AH AL BH BL = 40960 B
#define GSMEM    (3*STGB)               // 122880 B
#define KTILES   (H_/BK_)               // 128

__device__ __forceinline__ void hmma_load_stage(
    uint32_t sb, int s, const __nv_bfloat16* AH, const __nv_bfloat16* AL,
    const __nv_bfloat16* BH, const __nv_bfloat16* BL,
    int M0, int N0, int kt, int tid)
{
    uint32_t base = sb + s*STGB;
    #pragma unroll
    for (int i = 0; i < 2; ++i){
        int c = tid + (i << 8);          // 0..511
        int row = c >> 2, ch = c & 3;
        uint32_t soff = row*ROWB + (ch << 4);
        size_t ga = (size_t)(M0 + row)*H_ + kt*BK_ + (ch << 3);
        size_t gb = (size_t)(N0 + row)*H_ + kt*BK_ + (ch << 3);
        CP_ASYNC16(base + soff,          AH + ga);
        CP_ASYNC16(base + MATB + soff,   AL + ga);
        CP_ASYNC16(base + 2*MATB + soff, BH + gb);
        CP_ASYNC16(base + 3*MATB + soff, BL + gb);
    }
}

__global__ __launch_bounds__(256, 1)
void gemm_hmma_kernel(float* __restrict__ Cout, int asel, int bsel, int dest, int nheads)
{
    extern __shared__ char smem[];
    uint32_t sb = smem_to_u32(smem);
    const int tid = threadIdx.x;
    const int wid = tid >> 5, lane = tid & 31;
    const int wm = wid & 3, wn = wid >> 2;          // 4 x 2 warp grid
    const int M0 = blockIdx.y << 7, N0 = blockIdx.x << 7;

    const __nv_bfloat16 *AH = asel ? g_OH : g_hsH;
    const __nv_bfloat16 *AL = asel ? g_OL : g_hsL;
    const __nv_bfloat16 *BH, *BL;
    switch (bsel){
        case 0: BH = g_WqH; BL = g_WqL; break;
        case 1: BH = g_WkH; BL = g_WkL; break;
        case 2: BH = g_WvH; BL = g_WvL; break;
        default:BH = g_WoH; BL = g_WoL; break;
    }
    float* Cp;
    if      (dest == 0) Cp = g_Q;
    else if (dest == 1) Cp = g_K;
    else if (dest == 2) Cp = g_V;
    else                Cp = Cout;

    float acc[2][8][4];
    #pragma unroll
    for (int m = 0; m < 2; ++m)
        #pragma unroll
        for (int n = 0; n < 8; ++n)
            #pragma unroll
            for (int j = 0; j < 4; ++j) acc[m][n][j] = 0.f;

    // prologue: stages 0,1
    hmma_load_stage(sb, 0, AH, AL, BH, BL, M0, N0, 0, tid); CP_COMMIT();
    hmma_load_stage(sb, 1, AH, AL, BH, BL, M0, N0, 1, tid); CP_COMMIT();

    // ldmatrix address precompute (within-stage offsets)
    const uint32_t aRow = (uint32_t)(wm*32 + (lane & 15));
    const uint32_t aColB = (uint32_t)(((lane >> 4) << 3) * 2);      // bytes
    const uint32_t bRow = (uint32_t)(wn*64 + ((lane & 7) | ((lane & 16) >> 1)));
    const uint32_t bColB = (uint32_t)((((lane >> 3) & 1) << 3) * 2);

    #pragma unroll 1
    for (int kt = 0; kt < KTILES; ++kt){
        const int s = kt % 3;
        CP_WAIT1();
        __syncthreads();
        if (kt + 2 < KTILES){
            hmma_load_stage(sb, (kt + 2) % 3, AH, AL, BH, BL, M0, N0, kt + 2, tid);
        }
        CP_COMMIT();

        const uint32_t stA = sb + s*STGB;
        const uint32_t stB = stA + 2*MATB;
        #pragma unroll
        for (int ks = 0; ks < 2; ++ks){
            const uint32_t kB = (uint32_t)(ks << 5);   // 16 bf16 = 32 bytes
            uint32_t aHr[2][4], aLr[2][4];
            #pragma unroll
            for (int mm = 0; mm < 2; ++mm){
                uint32_t off = (aRow + mm*16)*ROWB + kB + aColB;
                LDSM_X4(aHr[mm], stA + off);
                LDSM_X4(aLr[mm], stA + MATB + off);
            }
            uint32_t bHr[16], bLr[16];
            #pragma unroll
            for (int g = 0; g < 4; ++g){
                uint32_t off = (bRow + g*16)*ROWB + kB + bColB;
                LDSM_X4(&bHr[g*4], stB + off);
                LDSM_X4(&bLr[g*4], stB + MATB + off);
            }
            #pragma unroll
            for (int mm = 0; mm < 2; ++mm){
                #pragma unroll
                for (int nn = 0; nn < 8; ++nn){
                    int bi = (nn >> 1)*4 + (nn & 1)*2;
                    MMA_BF16(acc[mm][nn], aHr[mm], bHr[bi], bHr[bi+1]);
                    MMA_BF16(acc[mm][nn], aHr[mm], bLr[bi], bLr[bi+1]);
                    MMA_BF16(acc[mm][nn], aLr[mm], bHr[bi], bHr[bi+1]);
                }
            }
        }
        __syncthreads();
    }

    // ---- epilogue ----
    const int rbase = M0 + wm*32 + (lane >> 2);
    const int cbase = wn*64 + (lane & 3)*2;       // relative to N0
    #pragma unroll
    for (int mm = 0; mm < 2; ++mm){
        #pragma unroll
        for (int half = 0; half < 2; ++half){
            int r = rbase + mm*16 + half*8;
            float* dst;
            if (dest == 3){
                dst = Cp + (size_t)r*H_ + N0 + cbase;
            } else {
                int bb = r >> 11, ss = r & (S_ - 1);
                dst = Cp + (((size_t)bb*nheads + blockIdx.x)*S_ + ss)*HD_ + cbase;
            }
            #pragma unroll
            for (int nn = 0; nn < 8; ++nn){
                float2 v;
                v.x = acc[mm][nn][half*2];
                v.y = acc[mm][nn][half*2 + 1];
                *(float2*)(dst + nn*8) = v;
            }
        }
    }
}

// ---------------- RoPE (in-place) ------------------------------------------
__global__ void rope_apply_kernel(int which, int rows){
    int idx = blockIdx.x * blockDim.x + threadIdx.x;
    if (idx >= (rows << 6)) return;
    float* X = which ? g_K : g_Q;
    int r = idx >> 6, j = idx & 63;
    int s = r & (S_ - 1);
    float c  = g_cos[(s << 6) + j];
    float sn = g_sin[(s << 6) + j];
    float* p = X + ((size_t)r << 7);
    float x1 = p[j], x2 = p[j + 64];
    p[j]      = x1 * c - x2 * sn;
    p[j + 64] = x2 * c + x1 * sn;
}

// ---------------- flash attention (non-causal, fp32) ------------------------
#define QK_LD 68
#define ATT_SMEM ((128*QK_LD + 128*QK_LD + 64*128 + 64*QK_LD) * 4)

__global__ __launch_bounds__(256, 1)
void attn_kernel(){
    extern __shared__ float sm[];
    float* Qs = sm;
    float* Ks = Qs + 128*QK_LD;
    float* Vs = Ks + 128*QK_LD;
    float* Ps = Vs + 64*128;

    const int tid = threadIdx.x;
    const int tx  = tid & 15, ty = tid >> 4;
    const int qb  = blockIdx.x;
    const int h   = blockIdx.y;
    const int b   = blockIdx.z;
    const int g   = h >> 2;

    const float* Qg = g_Q + (((size_t)b*NH_  + h)*S_ + (size_t)qb*64) * HD_;
    const float* Kg = g_K + (((size_t)b*NKV_ + g)*S_) * HD_;
    const float* Vg = g_V + (((size_t)b*NKV_ + g)*S_) * HD_;

    const float qscale = 0.08838834764831845f;
    #pragma unroll
    for (int t = tid; t < 64*32; t += 256){
        int row = t >> 5, dg = (t & 31) << 2;
        float4 v = *(const float4*)(Qg + (size_t)row*HD_ + dg);
        Qs[(dg+0)*QK_LD + row] = v.x * qscale;
        Qs[(dg+1)*QK_LD + row] = v.y * qscale;
        Qs[(dg+2)*QK_LD + row] = v.z * qscale;
        Qs[(dg+3)*QK_LD + row] = v.w * qscale;
    }

    float m_i[4], l_i[4];
    unsigned long long o2[4][4];
    #pragma unroll
    for (int qi = 0; qi < 4; ++qi){
        m_i[qi] = -INFINITY; l_i[qi] = 0.f;
        #pragma unroll
        for (int j = 0; j < 4; ++j) o2[qi][j] = 0ULL;
    }

    for (int kb = 0; kb < S_/64; ++kb){
        const float* Kt = Kg + (size_t)kb*64*HD_;
        const float* Vt = Vg + (size_t)kb*64*HD_;
        __syncthreads();
        #pragma unroll
        for (int t = tid; t < 64*32; t += 256){
            int row = t >> 5, dg = (t & 31) << 2;
            float4 kv = *(const float4*)(Kt + (size_t)row*HD_ + dg);
            Ks[(dg+0)*QK_LD + row] = kv.x;
            Ks[(dg+1)*QK_LD + row] = kv.y;
            Ks[(dg+2)*QK_LD + row] = kv.z;
            Ks[(dg+3)*QK_LD + row] = kv.w;
            *(float4*)(Vs + (size_t)row*HD_ + dg) = *(const float4*)(Vt + (size_t)row*HD_ + dg);
        }
        __syncthreads();

        unsigned long long s2[4][2];
        #pragma unroll
        for (int qi = 0; qi < 4; ++qi){ s2[qi][0] = 0ULL; s2[qi][1] = 0ULL; }
        #pragma unroll 4
        for (int d = 0; d < 128; ++d){
            const float* qrow = Qs + d*QK_LD;
            const float* krow = Ks + d*QK_LD;
            float4 q = *(const float4*)(qrow + (ty << 2));
            unsigned long long k0 = *(const unsigned long long*)(krow + (tx << 2));
            unsigned long long k1 = *(const unsigned long long*)(krow + (tx << 2) + 2);
            float qv[4] = {q.x, q.y, q.z, q.w};
            #pragma unroll
            for (int qi = 0; qi < 4; ++qi){
                unsigned long long qd = pack2(qv[qi], qv[qi]);
                FMA2(s2[qi][0], qd, k0);
                FMA2(s2[qi][1], qd, k1);
            }
        }

        #pragma unroll
        for (int qi = 0; qi < 4; ++qi){
            float2 sa = unpack2(s2[qi][0]);
            float2 sb2 = unpack2(s2[qi][1]);
            float sv[4] = {sa.x, sa.y, sb2.x, sb2.y};
            float mb = fmaxf(fmaxf(sv[0], sv[1]), fmaxf(sv[2], sv[3]));
            #pragma unroll
            for (int off = 8; off; off >>= 1)
                mb = fmaxf(mb, __shfl_xor_sync(0xffffffffu, mb, off));
            float mn = fmaxf(m_i[qi], mb);
            float corr = __expf(m_i[qi] - mn);
            m_i[qi] = mn;
            float ls = 0.f;
            #pragma unroll
            for (int kj = 0; kj < 4; ++kj){
                float p = __expf(sv[kj] - mn);
                ls += p;
                Ps[((tx << 2) + kj)*QK_LD + (ty << 2) + qi] = p;
            }
            #pragma unroll
            for (int off = 8; off; off >>= 1)
                ls += __shfl_xor_sync(0xffffffffu, ls, off);
            l_i[qi] = l_i[qi] * corr + ls;
            unsigned long long c2 = pack2(corr, corr);
            #pragma unroll
            for (int j = 0; j < 4; ++j) MUL2(o2[qi][j], c2);
        }
        __syncthreads();

        #pragma unroll 2
        for (int k = 0; k < 64; ++k){
            float4 pv = *(const float4*)(Ps + k*QK_LD + (ty << 2));
            const float* vrow = Vs + (k << 7);
            unsigned long long v0 = *(const unsigned long long*)(vrow + (tx << 1));
            unsigned long long v1 = *(const unsigned long long*)(vrow + (tx << 1) + 32);
            unsigned long long v2 = *(const unsigned long long*)(vrow + (tx << 1) + 64);
            unsigned long long v3 = *(const unsigned long long*)(vrow + (tx << 1) + 96);
            float pf[4] = {pv.x, pv.y, pv.z, pv.w};
            #pragma unroll
            for (int qi = 0; qi < 4; ++qi){
                unsigned long long pd = pack2(pf[qi], pf[qi]);
                FMA2(o2[qi][0], pd, v0);
                FMA2(o2[qi][1], pd, v1);
                FMA2(o2[qi][2], pd, v2);
                FMA2(o2[qi][3], pd, v3);
            }
        }
    }

    // epilogue: normalize, split to bf16 hi/lo at [b, s, h*128 + d]
    size_t obase = ((size_t)b*S_ + (size_t)qb*64) * H_ + (size_t)h*HD_;
    #pragma unroll
    for (int qi = 0; qi < 4; ++qi){
        float inv = 1.0f / l_i[qi];
        int row = (ty << 2) + qi;
        #pragma unroll
        for (int j = 0; j < 4; ++j){
            float2 v = unpack2(o2[qi][j]);
            v.x *= inv; v.y *= inv;
            int d = (tx << 1) + (j << 5);
            size_t idx = obase + (size_t)row*H_ + d;
            __nv_bfloat16 hx = __float2bfloat16(v.x), hy = __float2bfloat16(v.y);
            __nv_bfloat16 lx = __float2bfloat16(v.x - __bfloat162float(hx));
            __nv_bfloat16 ly = __float2bfloat16(v.y - __bfloat162float(hy));
            __nv_bfloat162 hh; hh.x = hx; hh.y = hy;
            __nv_bfloat162 ll; ll.x = lx; ll.y = ly;
            *(__nv_bfloat162*)(g_OH + idx) = hh;
            *(__nv_bfloat162*)(g_OL + idx) = ll;
        }
    }
}

// ---------------- launch ----------------------------------------------------
extern "C" void kernel_launch(void* const* d_in, const int* in_sizes, int n_in,
                              void* d_out, int out_size)
{
    const float* hs = (const float*)d_in[0];
    const float* Wq = (const float*)d_in[1];
    const float* Wk = (const float*)d_in[2];
    const float* Wv = (const float*)d_in[3];
    const float* Wo = (const float*)d_in[4];
    float* out = (float*)d_out;

    rope_tables_kernel<<<(S_*64 + 255)/256, 256>>>();

    split_kernel<<<(TOK*H_/4 + 255)/256, 256>>>(hs, TOK*H_, 0);
    split_kernel<<<(NH_*HD_*H_/4 + 255)/256, 256>>>(Wq, NH_*HD_*H_, 1);
    split_kernel<<<(NKV_*HD_*H_/4 + 255)/256, 256>>>(Wk, NKV_*HD_*H_, 2);
    split_kernel<<<(NKV_*HD_*H_/4 + 255)/256, 256>>>(Wv, NKV_*HD_*H_, 3);
    split_kernel<<<(H_*H_/4 + 255)/256, 256>>>(Wo, H_*H_, 4);

    cudaFuncSetAttribute(gemm_hmma_kernel, cudaFuncAttributeMaxDynamicSharedMemorySize, GSMEM);

    // projections (HMMA, head-major store)
    gemm_hmma_kernel<<<dim3(32, 32), 256, GSMEM>>>(nullptr, 0, 0, 0, NH_);
    gemm_hmma_kernel<<<dim3(8,  32), 256, GSMEM>>>(nullptr, 0, 1, 1, NKV_);
    gemm_hmma_kernel<<<dim3(8,  32), 256, GSMEM>>>(nullptr, 0, 2, 2, NKV_);

    // RoPE in place
    rope_apply_kernel<<<(B_*NH_*S_*64)/256,  256>>>(0, B_*NH_*S_);
    rope_apply_kernel<<<(B_*NKV_*S_*64)/256, 256>>>(1, B_*NKV_*S_);

    // attention (writes bf16 hi/lo O)
    cudaFuncSetAttribute(attn_kernel, cudaFuncAttributeMaxDynamicSharedMemorySize, ATT_SMEM);
    attn_kernel<<<dim3(S_/64, NH_, B_), 256, ATT_SMEM>>>();

    // output projection (HMMA) -> d_out
    gemm_hmma_kernel<<<dim3(32, 32), 256, GSMEM>>>(out, 1, 3, 3, 0);
}

// round 4
// speedup vs baseline: 2.6135x; 1.7376x over previous
#include <cuda_runtime.h>
#include <cuda_bf16.h>
#include <math.h>
#include <stdint.h>

#define B_   2
#define S_   2048
#define H_   4096
#define NH_  32
#define NKV_ 8
#define HD_  128
#define TOK  (B_*S_)        // 4096

// ---------------- scratch (static device globals; no allocation) ----------
__device__ float g_Q[(size_t)B_*NH_*S_*HD_];
__device__ float g_K[(size_t)B_*NKV_*S_*HD_];
__device__ float g_V[(size_t)B_*NKV_*S_*HD_];
__device__ float g_cos[S_*64];
__device__ float g_sin[S_*64];

// bf16 hi/lo split buffers
__device__ __nv_bfloat16 g_hsH[(size_t)TOK*H_], g_hsL[(size_t)TOK*H_];
__device__ __nv_bfloat16 g_WqH[(size_t)NH_*HD_*H_],  g_WqL[(size_t)NH_*HD_*H_];
__device__ __nv_bfloat16 g_WkH[(size_t)NKV_*HD_*H_], g_WkL[(size_t)NKV_*HD_*H_];
__device__ __nv_bfloat16 g_WvH[(size_t)NKV_*HD_*H_], g_WvL[(size_t)NKV_*HD_*H_];
__device__ __nv_bfloat16 g_WoH[(size_t)H_*H_],       g_WoL[(size_t)H_*H_];
__device__ __nv_bfloat16 g_OH[(size_t)TOK*H_],       g_OL[(size_t)TOK*H_];

// attention operands (bf16 hi/lo, RoPE and scale pre-applied)
__device__ __nv_bfloat16 g_QbH[(size_t)B_*NH_*S_*HD_],  g_QbL[(size_t)B_*NH_*S_*HD_];
__device__ __nv_bfloat16 g_KbH[(size_t)B_*NKV_*S_*HD_], g_KbL[(size_t)B_*NKV_*S_*HD_];
__device__ __nv_bfloat16 g_VbH[(size_t)B_*NKV_*S_*HD_], g_VbL[(size_t)B_*NKV_*S_*HD_];

// ---------------- helpers ----------------------------------------------------
__device__ __forceinline__ uint32_t smem_to_u32(const void* p){
    uint32_t a;
    asm("{ .reg .u64 t; cvta.to.shared.u64 t, %1; cvt.u32.u64 %0, t; }" : "=r"(a) : "l"(p));
    return a;
}
#define CP_ASYNC16(dst, src) \
    asm volatile("cp.async.cg.shared.global [%0], [%1], 16;" :: "r"(dst), "l"(src))
#define CP_COMMIT() asm volatile("cp.async.commit_group;" ::: "memory")
#define CP_WAIT1()  asm volatile("cp.async.wait_group 1;" ::: "memory")
#define CP_WAIT0()  asm volatile("cp.async.wait_group 0;" ::: "memory")

#define LDSM_X4(r, addr) \
    asm volatile("ldmatrix.sync.aligned.m8n8.x4.shared.b16 {%0,%1,%2,%3}, [%4];" \
        : "=r"((r)[0]),"=r"((r)[1]),"=r"((r)[2]),"=r"((r)[3]) : "r"(addr))
#define LDSM_X4_T(r, addr) \
    asm volatile("ldmatrix.sync.aligned.m8n8.x4.trans.shared.b16 {%0,%1,%2,%3}, [%4];" \
        : "=r"((r)[0]),"=r"((r)[1]),"=r"((r)[2]),"=r"((r)[3]) : "r"(addr))

#define MMA_BF16(c, a, b0, b1) \
    asm volatile("mma.sync.aligned.m16n8k16.row.col.f32.bf16.bf16.f32 " \
        "{%0,%1,%2,%3},{%4,%5,%6,%7},{%8,%9},{%0,%1,%2,%3};" \
        : "+f"((c)[0]),"+f"((c)[1]),"+f"((c)[2]),"+f"((c)[3]) \
        : "r"((a)[0]),"r"((a)[1]),"r"((a)[2]),"r"((a)[3]), "r"(b0),"r"(b1))

__device__ __forceinline__ uint32_t cvt_bf16x2(float lo, float hi){
    uint32_t d;
    asm("cvt.rn.bf16x2.f32 %0, %1, %2;" : "=r"(d) : "f"(hi), "f"(lo));
    return d;
}
// split (x,y) into bf16x2 hi pair + bf16x2 residual pair
__device__ __forceinline__ void split_pair(float x, float y, uint32_t& h2, uint32_t& l2){
    h2 = cvt_bf16x2(x, y);
    float xh = __int_as_float(h2 << 16);
    float yh = __int_as_float(h2 & 0xFFFF0000u);
    l2 = cvt_bf16x2(x - xh, y - yh);
}
// fast e^x on FMA/ALU pipes (avoids MUFU). valid for x <= 0, clamps below -87.
__device__ __forceinline__ float fast_exp(float x){
    x = fmaxf(x, -87.0f);
    float y = x * 1.4426950408889634f;
    float r = __fadd_rn(y, 12582912.0f);       // round y to nearest int
    float f = y - __fadd_rn(r, -12582912.0f);  // f in [-0.5, 0.5]
    float p = 1.5403530e-4f;
    p = __fmaf_rn(p, f, 1.3333558e-3f);
    p = __fmaf_rn(p, f, 9.6181291e-3f);
    p = __fmaf_rn(p, f, 5.5504109e-2f);
    p = __fmaf_rn(p, f, 2.4022651e-1f);
    p = __fmaf_rn(p, f, 6.9314718e-1f);
    p = __fmaf_rn(p, f, 1.0f);
    int n = __float_as_int(r) - 0x4B400000;
    return __int_as_float(__float_as_int(p) + (n << 23));
}

// ---------------- rope tables ----------------------------------------------
__global__ void rope_tables_kernel(){
    int idx = blockIdx.x * blockDim.x + threadIdx.x;
    if (idx >= S_*64) return;
    int s = idx >> 6, j = idx & 63;
    double inv = pow(500000.0, -((double)j)/64.0);
    float ang = (float)s * (float)inv;
    g_cos[idx] = (float)cos((double)ang);
    g_sin[idx] = (float)sin((double)ang);
}

// ---------------- fp32 -> bf16 hi/lo split ----------------------------------
__global__ void split_kernel(const float* __restrict__ src, int n, int dsel){
    __nv_bfloat16 *dH, *dL;
    switch (dsel){
        case 0: dH = g_hsH; dL = g_hsL; break;
        case 1: dH = g_WqH; dL = g_WqL; break;
        case 2: dH = g_WkH; dL = g_WkL; break;
        case 3: dH = g_WvH; dL = g_WvL; break;
        case 4: dH = g_WoH; dL = g_WoL; break;
        default:dH = g_VbH; dL = g_VbL; break;
    }
    int i = (blockIdx.x * blockDim.x + threadIdx.x) << 2;
    if (i >= n) return;
    const float* sp = (dsel == 5) ? (const float*)g_V : src;
    float4 v = *(const float4*)(sp + i);
    uint32_t h0, l0, h1, l1;
    split_pair(v.x, v.y, h0, l0);
    split_pair(v.z, v.w, h1, l1);
    *(uint32_t*)(dH + i)     = h0;
    *(uint32_t*)(dH + i + 2) = h1;
    *(uint32_t*)(dL + i)     = l0;
    *(uint32_t*)(dL + i + 2) = l1;
}

// ---------------- RoPE + scale + bf16 split (Q and K) ------------------------
__global__ void rope_convert_kernel(int which, int rows){
    int idx = blockIdx.x * blockDim.x + threadIdx.x;
    if (idx >= (rows << 6)) return;
    int r = idx >> 6, j = idx & 63;
    int s = r & (S_ - 1);
    const float* X = which ? g_K : g_Q;
    float c  = g_cos[(s << 6) + j];
    float sn = g_sin[(s << 6) + j];
    float x1 = X[((size_t)r << 7) + j], x2 = X[((size_t)r << 7) + j + 64];
    float y1 = x1 * c - x2 * sn;
    float y2 = x2 * c + x1 * sn;
    if (!which){ y1 *= 0.08838834764831845f; y2 *= 0.08838834764831845f; }
    __nv_bfloat16 *dH = which ? g_KbH : g_QbH;
    __nv_bfloat16 *dL = which ? g_KbL : g_QbL;
    __nv_bfloat16 h1b = __float2bfloat16(y1);
    __nv_bfloat16 h2b = __float2bfloat16(y2);
    dH[((size_t)r << 7) + j]      = h1b;
    dH[((size_t)r << 7) + j + 64] = h2b;
    dL[((size_t)r << 7) + j]      = __float2bfloat16(y1 - __bfloat162float(h1b));
    dL[((size_t)r << 7) + j + 64] = __float2bfloat16(y2 - __bfloat162float(h2b));
}

// ---------------- HMMA GEMM: C[M,N] = A[M,K]*B[N,K]^T, bf16 3-pass split ----
#define BK_      32
#define ROWB     80
#define MATB     (128*ROWB)
#define STGB     (4*MATB)
#define GSMEM    (3*STGB)
#define KTILES   (H_/BK_)

__device__ __forceinline__ void hmma_load_stage(
    uint32_t sb, int s, const __nv_bfloat16* AH, const __nv_bfloat16* AL,
    const __nv_bfloat16* BH, const __nv_bfloat16* BL,
    int M0, int N0, int kt, int tid)
{
    uint32_t base = sb + s*STGB;
    #pragma unroll
    for (int i = 0; i < 2; ++i){
        int c = tid + (i << 8);
        int row = c >> 2, ch = c & 3;
        uint32_t soff = row*ROWB + (ch << 4);
        size_t ga = (size_t)(M0 + row)*H_ + kt*BK_ + (ch << 3);
        size_t gb = (size_t)(N0 + row)*H_ + kt*BK_ + (ch << 3);
        CP_ASYNC16(base + soff,          AH + ga);
        CP_ASYNC16(base + MATB + soff,   AL + ga);
        CP_ASYNC16(base + 2*MATB + soff, BH + gb);
        CP_ASYNC16(base + 3*MATB + soff, BL + gb);
    }
}

__global__ __launch_bounds__(256, 1)
void gemm_hmma_kernel(float* __restrict__ Cout, int asel, int bsel, int dest, int nheads)
{
    extern __shared__ char smem[];
    uint32_t sb = smem_to_u32(smem);
    const int tid = threadIdx.x;
    const int wid = tid >> 5, lane = tid & 31;
    const int wm = wid & 3, wn = wid >> 2;
    const int M0 = blockIdx.y << 7, N0 = blockIdx.x << 7;

    const __nv_bfloat16 *AH = asel ? g_OH : g_hsH;
    const __nv_bfloat16 *AL = asel ? g_OL : g_hsL;
    const __nv_bfloat16 *BH, *BL;
    switch (bsel){
        case 0: BH = g_WqH; BL = g_WqL; break;
        case 1: BH = g_WkH; BL = g_WkL; break;
        case 2: BH = g_WvH; BL = g_WvL; break;
        default:BH = g_WoH; BL = g_WoL; break;
    }
    float* Cp;
    if      (dest == 0) Cp = g_Q;
    else if (dest == 1) Cp = g_K;
    else if (dest == 2) Cp = g_V;
    else                Cp = Cout;

    float acc[2][8][4];
    #pragma unroll
    for (int m = 0; m < 2; ++m)
        #pragma unroll
        for (int n = 0; n < 8; ++n)
            #pragma unroll
            for (int j = 0; j < 4; ++j) acc[m][n][j] = 0.f;

    hmma_load_stage(sb, 0, AH, AL, BH, BL, M0, N0, 0, tid); CP_COMMIT();
    hmma_load_stage(sb, 1, AH, AL, BH, BL, M0, N0, 1, tid); CP_COMMIT();

    const uint32_t aRow = (uint32_t)(wm*32 + (lane & 15));
    const uint32_t aColB = (uint32_t)(((lane >> 4) << 3) * 2);
    const uint32_t bRow = (uint32_t)(wn*64 + ((lane & 7) | ((lane & 16) >> 1)));
    const uint32_t bColB = (uint32_t)((((lane >> 3) & 1) << 3) * 2);

    #pragma unroll 1
    for (int kt = 0; kt < KTILES; ++kt){
        const int s = kt % 3;
        CP_WAIT1();
        __syncthreads();
        if (kt + 2 < KTILES){
            hmma_load_stage(sb, (kt + 2) % 3, AH, AL, BH, BL, M0, N0, kt + 2, tid);
        }
        CP_COMMIT();

        const uint32_t stA = sb + s*STGB;
        const uint32_t stB = stA + 2*MATB;
        #pragma unroll
        for (int ks = 0; ks < 2; ++ks){
            const uint32_t kB = (uint32_t)(ks << 5);
            uint32_t aHr[2][4], aLr[2][4];
            #pragma unroll
            for (int mm = 0; mm < 2; ++mm){
                uint32_t off = (aRow + mm*16)*ROWB + kB + aColB;
                LDSM_X4(aHr[mm], stA + off);
                LDSM_X4(aLr[mm], stA + MATB + off);
            }
            uint32_t bHr[16], bLr[16];
            #pragma unroll
            for (int g = 0; g < 4; ++g){
                uint32_t off = (bRow + g*16)*ROWB + kB + bColB;
                LDSM_X4(&bHr[g*4], stB + off);
                LDSM_X4(&bLr[g*4], stB + MATB + off);
            }
            #pragma unroll
            for (int mm = 0; mm < 2; ++mm){
                #pragma unroll
                for (int nn = 0; nn < 8; ++nn){
                    int bi = (nn >> 1)*4 + (nn & 1)*2;
                    MMA_BF16(acc[mm][nn], aHr[mm], bHr[bi], bHr[bi+1]);
                    MMA_BF16(acc[mm][nn], aHr[mm], bLr[bi], bLr[bi+1]);
                    MMA_BF16(acc[mm][nn], aLr[mm], bHr[bi], bHr[bi+1]);
                }
            }
        }
        __syncthreads();
    }

    const int rbase = M0 + wm*32 + (lane >> 2);
    const int cbase = wn*64 + (lane & 3)*2;
    #pragma unroll
    for (int mm = 0; mm < 2; ++mm){
        #pragma unroll
        for (int half = 0; half < 2; ++half){
            int r = rbase + mm*16 + half*8;
            float* dst;
            if (dest == 3){
                dst = Cp + (size_t)r*H_ + N0 + cbase;
            } else {
                int bb = r >> 11, ss = r & (S_ - 1);
                dst = Cp + (((size_t)bb*nheads + blockIdx.x)*S_ + ss)*HD_ + cbase;
            }
            #pragma unroll
            for (int nn = 0; nn < 8; ++nn){
                float2 v;
                v.x = acc[mm][nn][half*2];
                v.y = acc[mm][nn][half*2 + 1];
                *(float2*)(dst + nn*8) = v;
            }
        }
    }
}

// ---------------- HMMA flash attention --------------------------------------
// Q-tile 128 rows (8 warps x 16), K-tile 64 keys, bf16 hi/lo 3-pass.
#define AROWB 272                       // 128 bf16 (256B) + 16B pad
#define AQMAT (128*AROWB)               // 34816
#define AKMAT (64*AROWB)                // 17408
#define ASTGB (4*AKMAT)                 // KH KL VH VL = 69632
#define ASMEM (2*AQMAT + 2*ASTGB)       // 208896

__device__ __forceinline__ void attn_load_kv(
    uint32_t st, const __nv_bfloat16* KH, const __nv_bfloat16* KL,
    const __nv_bfloat16* VH, const __nv_bfloat16* VL, int key0, int tid)
{
    #pragma unroll
    for (int i = 0; i < 16; ++i){
        int c = tid + (i << 8);
        int mat = c >> 10;
        int cc = c & 1023;
        int row = cc >> 4, ch = cc & 15;
        uint32_t dst = st + mat*AKMAT + row*AROWB + (ch << 4);
        const __nv_bfloat16* src = (mat == 0) ? KH : (mat == 1) ? KL : (mat == 2) ? VH : VL;
        CP_ASYNC16(dst, src + (size_t)(key0 + row)*HD_ + (ch << 3));
    }
}

__global__ __launch_bounds__(256, 1)
void attn_mma_kernel(){
    extern __shared__ char smem[];
    uint32_t sb = smem_to_u32(smem);
    const int tid = threadIdx.x;
    const int wid = tid >> 5, lane = tid & 31;
    const int qb = blockIdx.x, h = blockIdx.y, b = blockIdx.z;
    const int g = h >> 2;

    const __nv_bfloat16* QHg = g_QbH + (((size_t)b*NH_ + h)*S_ + (size_t)qb*128)*HD_;
    const __nv_bfloat16* QLg = g_QbL + (((size_t)b*NH_ + h)*S_ + (size_t)qb*128)*HD_;
    const __nv_bfloat16* KHg = g_KbH + ((size_t)b*NKV_ + g)*S_*HD_;
    const __nv_bfloat16* KLg = g_KbL + ((size_t)b*NKV_ + g)*S_*HD_;
    const __nv_bfloat16* VHg = g_VbH + ((size_t)b*NKV_ + g)*S_*HD_;
    const __nv_bfloat16* VLg = g_VbL + ((size_t)b*NKV_ + g)*S_*HD_;

    const uint32_t QH0 = sb, QL0 = sb + AQMAT;

    // Q load (once)
    #pragma unroll
    for (int i = 0; i < 16; ++i){
        int c = tid + (i << 8);
        int mat = c >> 11;
        int cc = c & 2047;
        int row = cc >> 4, ch = cc & 15;
        uint32_t dst = (mat ? QL0 : QH0) + row*AROWB + (ch << 4);
        const __nv_bfloat16* src = mat ? QLg : QHg;
        CP_ASYNC16(dst, src + (size_t)row*HD_ + (ch << 3));
    }
    // stage 0 K/V
    attn_load_kv(sb + 2*AQMAT, KHg, KLg, VHg, VLg, 0, tid);
    CP_COMMIT();

    float m0 = -1e30f, m1 = -1e30f, l0 = 0.f, l1 = 0.f;
    float O[16][4];
    #pragma unroll
    for (int nt = 0; nt < 16; ++nt)
        #pragma unroll
        for (int j = 0; j < 4; ++j) O[nt][j] = 0.f;

    const uint32_t aOff  = (uint32_t)(wid*16 + (lane & 15))*AROWB + ((lane >> 4) << 4);
    const uint32_t bOffK = (uint32_t)((lane & 7) | ((lane & 16) >> 1))*AROWB + (((lane >> 3) & 1) << 4);
    const uint32_t vOff  = (uint32_t)((lane & 7) + (lane & 8))*AROWB + ((lane >> 4) << 4);

    #pragma unroll 1
    for (int kb = 0; kb < S_/64; ++kb){
        const int s = kb & 1;
        const uint32_t KH = sb + 2*AQMAT + s*ASTGB;
        const uint32_t KL = KH + AKMAT, VH = KH + 2*AKMAT, VL = KH + 3*AKMAT;

        CP_WAIT0();
        __syncthreads();
        if (kb + 1 < S_/64)
            attn_load_kv(sb + 2*AQMAT + (s^1)*ASTGB, KHg, KLg, VHg, VLg, (kb+1)*64, tid);
        CP_COMMIT();

        // ---- S = Q K^T (3-pass) ----
        float Sa[8][4];
        #pragma unroll
        for (int nt = 0; nt < 8; ++nt)
            #pragma unroll
            for (int j = 0; j < 4; ++j) Sa[nt][j] = 0.f;

        #pragma unroll
        for (int ks = 0; ks < 8; ++ks){
            uint32_t aH[4], aL[4];
            LDSM_X4(aH, QH0 + aOff + ks*32);
            LDSM_X4(aL, QL0 + aOff + ks*32);
            #pragma unroll
            for (int gi = 0; gi < 4; ++gi){
                uint32_t bH[4], bL[4];
                uint32_t off = bOffK + gi*(16*AROWB) + ks*32;
                LDSM_X4(bH, KH + off);
                LDSM_X4(bL, KL + off);
                MMA_BF16(Sa[2*gi],   aH, bH[0], bH[1]);
                MMA_BF16(Sa[2*gi],   aH, bL[0], bL[1]);
                MMA_BF16(Sa[2*gi],   aL, bH[0], bH[1]);
                MMA_BF16(Sa[2*gi+1], aH, bH[2], bH[3]);
                MMA_BF16(Sa[2*gi+1], aH, bL[2], bL[3]);
                MMA_BF16(Sa[2*gi+1], aL, bH[2], bH[3]);
            }
        }

        // ---- online softmax (rows r=lane>>2 and r+8) ----
        float mb0 = -1e30f, mb1 = -1e30f;
        #pragma unroll
        for (int nt = 0; nt < 8; ++nt){
            mb0 = fmaxf(mb0, fmaxf(Sa[nt][0], Sa[nt][1]));
            mb1 = fmaxf(mb1, fmaxf(Sa[nt][2], Sa[nt][3]));
        }
        mb0 = fmaxf(mb0, __shfl_xor_sync(0xffffffffu, mb0, 1));
        mb0 = fmaxf(mb0, __shfl_xor_sync(0xffffffffu, mb0, 2));
        mb1 = fmaxf(mb1, __shfl_xor_sync(0xffffffffu, mb1, 1));
        mb1 = fmaxf(mb1, __shfl_xor_sync(0xffffffffu, mb1, 2));
        float m0n = fmaxf(m0, mb0), m1n = fmaxf(m1, mb1);
        float corr0 = fast_exp(m0 - m0n), corr1 = fast_exp(m1 - m1n);
        m0 = m0n; m1 = m1n;

        float ls0 = 0.f, ls1 = 0.f;
        #pragma unroll
        for (int nt = 0; nt < 8; ++nt){
            Sa[nt][0] = fast_exp(Sa[nt][0] - m0);
            Sa[nt][1] = fast_exp(Sa[nt][1] - m0);
            Sa[nt][2] = fast_exp(Sa[nt][2] - m1);
            Sa[nt][3] = fast_exp(Sa[nt][3] - m1);
            ls0 += Sa[nt][0] + Sa[nt][1];
            ls1 += Sa[nt][2] + Sa[nt][3];
        }
        ls0 += __shfl_xor_sync(0xffffffffu, ls0, 1);
        ls0 += __shfl_xor_sync(0xffffffffu, ls0, 2);
        ls1 += __shfl_xor_sync(0xffffffffu, ls1, 1);
        ls1 += __shfl_xor_sync(0xffffffffu, ls1, 2);
        l0 = l0*corr0 + ls0;
        l1 = l1*corr1 + ls1;

        #pragma unroll
        for (int nt = 0; nt < 16; ++nt){
            O[nt][0] *= corr0; O[nt][1] *= corr0;
            O[nt][2] *= corr1; O[nt][3] *= corr1;
        }

        // ---- P -> A fragments (bf16 hi/lo) ----
        uint32_t aPh[4][4], aPl[4][4];
        #pragma unroll
        for (int kt = 0; kt < 4; ++kt){
            split_pair(Sa[2*kt][0],   Sa[2*kt][1],   aPh[kt][0], aPl[kt][0]);
            split_pair(Sa[2*kt][2],   Sa[2*kt][3],   aPh[kt][1], aPl[kt][1]);
            split_pair(Sa[2*kt+1][0], Sa[2*kt+1][1], aPh[kt][2], aPl[kt][2]);
            split_pair(Sa[2*kt+1][2], Sa[2*kt+1][3], aPh[kt][3], aPl[kt][3]);
        }

        // ---- O += P V (3-pass, V via ldmatrix.trans) ----
        #pragma unroll
        for (int kt = 0; kt < 4; ++kt){
            #pragma unroll
            for (int dp = 0; dp < 8; ++dp){
                uint32_t bVh[4], bVl[4];
                uint32_t off = vOff + kt*(16*AROWB) + dp*32;
                LDSM_X4_T(bVh, VH + off);
                LDSM_X4_T(bVl, VL + off);
                MMA_BF16(O[2*dp],   aPh[kt], bVh[0], bVh[1]);
                MMA_BF16(O[2*dp],   aPl[kt], bVh[0], bVh[1]);
                MMA_BF16(O[2*dp],   aPh[kt], bVl[0], bVl[1]);
                MMA_BF16(O[2*dp+1], aPh[kt], bVh[2], bVh[3]);
                MMA_BF16(O[2*dp+1], aPl[kt], bVh[2], bVh[3]);
                MMA_BF16(O[2*dp+1], aPh[kt], bVl[2], bVl[3]);
            }
        }
    }

    // ---- epilogue: normalize, bf16 hi/lo to g_OH/g_OL ----
    const float inv0 = 1.0f / l0, inv1 = 1.0f / l1;
    const int s0 = qb*128 + wid*16 + (lane >> 2);
    const size_t ob = (size_t)b*S_*H_ + (size_t)h*HD_;
    #pragma unroll
    for (int nt = 0; nt < 16; ++nt){
        int d = nt*8 + (lane & 3)*2;
        uint32_t h2, l2;
        split_pair(O[nt][0]*inv0, O[nt][1]*inv0, h2, l2);
        size_t idx0 = ob + (size_t)s0*H_ + d;
        *(uint32_t*)(g_OH + idx0) = h2;
        *(uint32_t*)(g_OL + idx0) = l2;
        split_pair(O[nt][2]*inv1, O[nt][3]*inv1, h2, l2);
        size_t idx1 = ob + (size_t)(s0 + 8)*H_ + d;
        *(uint32_t*)(g_OH + idx1) = h2;
        *(uint32_t*)(g_OL + idx1) = l2;
    }
}

// ---------------- launch ----------------------------------------------------
extern "C" void kernel_launch(void* const* d_in, const int* in_sizes, int n_in,
                              void* d_out, int out_size)
{
    const float* hs = (const float*)d_in[0];
    const float* Wq = (const float*)d_in[1];
    const float* Wk = (const float*)d_in[2];
    const float* Wv = (const float*)d_in[3];
    const float* Wo = (const float*)d_in[4];
    float* out = (float*)d_out;

    rope_tables_kernel<<<(S_*64 + 255)/256, 256>>>();

    split_kernel<<<(TOK*H_/4 + 255)/256, 256>>>(hs, TOK*H_, 0);
    split_kernel<<<(NH_*HD_*H_/4 + 255)/256, 256>>>(Wq, NH_*HD_*H_, 1);
    split_kernel<<<(NKV_*HD_*H_/4 + 255)/256, 256>>>(Wk, NKV_*HD_*H_, 2);
    split_kernel<<<(NKV_*HD_*H_/4 + 255)/256, 256>>>(Wv, NKV_*HD_*H_, 3);
    split_kernel<<<(H_*H_/4 + 255)/256, 256>>>(Wo, H_*H_, 4);

    cudaFuncSetAttribute(gemm_hmma_kernel, cudaFuncAttributeMaxDynamicSharedMemorySize, GSMEM);

    gemm_hmma_kernel<<<dim3(32, 32), 256, GSMEM>>>(nullptr, 0, 0, 0, NH_);
    gemm_hmma_kernel<<<dim3(8,  32), 256, GSMEM>>>(nullptr, 0, 1, 1, NKV_);
    gemm_hmma_kernel<<<dim3(8,  32), 256, GSMEM>>>(nullptr, 0, 2, 2, NKV_);

    // RoPE + scale + bf16 split for attention operands
    rope_convert_kernel<<<(B_*NH_*S_*64)/256,  256>>>(0, B_*NH_*S_);
    rope_convert_kernel<<<(B_*NKV_*S_*64)/256, 256>>>(1, B_*NKV_*S_);
    split_kernel<<<(B_*NKV_*S_*HD_/4 + 255)/256, 256>>>(nullptr, B_*NKV_*S_*HD_, 5);

    // HMMA flash attention
    cudaFuncSetAttribute(attn_mma_kernel, cudaFuncAttributeMaxDynamicSharedMemorySize, ASMEM);
    attn_mma_kernel<<<dim3(S_/128, NH_, B_), 256, ASMEM>>>();

    // output projection -> d_out
    gemm_hmma_kernel<<<dim3(32, 32), 256, GSMEM>>>(out, 1, 3, 3, 0);
}

// round 5
// speedup vs baseline: 2.9709x; 1.1368x over previous
#include <cuda_runtime.h>
#include <cuda_bf16.h>
#include <math.h>
#include <stdint.h>

#define B_   2
#define S_   2048
#define H_   4096
#define NH_  32
#define NKV_ 8
#define HD_  128
#define TOK  (B_*S_)        // 4096

// ---------------- scratch (static device globals; no allocation) ----------
__device__ float g_Q[(size_t)B_*NH_*S_*HD_];
__device__ float g_K[(size_t)B_*NKV_*S_*HD_];
__device__ float g_cos[S_*64];
__device__ float g_sin[S_*64];

// bf16 hi/lo split buffers
__device__ __nv_bfloat16 g_hsH[(size_t)TOK*H_], g_hsL[(size_t)TOK*H_];
__device__ __nv_bfloat16 g_WqH[(size_t)NH_*HD_*H_],  g_WqL[(size_t)NH_*HD_*H_];
__device__ __nv_bfloat16 g_WkH[(size_t)NKV_*HD_*H_], g_WkL[(size_t)NKV_*HD_*H_];
__device__ __nv_bfloat16 g_WvH[(size_t)NKV_*HD_*H_], g_WvL[(size_t)NKV_*HD_*H_];
__device__ __nv_bfloat16 g_WoH[(size_t)H_*H_],       g_WoL[(size_t)H_*H_];
__device__ __nv_bfloat16 g_OH[(size_t)TOK*H_],       g_OL[(size_t)TOK*H_];

// attention operands (bf16 hi/lo, RoPE and scale pre-applied)
__device__ __nv_bfloat16 g_QbH[(size_t)B_*NH_*S_*HD_],  g_QbL[(size_t)B_*NH_*S_*HD_];
__device__ __nv_bfloat16 g_KbH[(size_t)B_*NKV_*S_*HD_], g_KbL[(size_t)B_*NKV_*S_*HD_];
__device__ __nv_bfloat16 g_VbH[(size_t)B_*NKV_*S_*HD_], g_VbL[(size_t)B_*NKV_*S_*HD_];

// ---------------- helpers ----------------------------------------------------
__device__ __forceinline__ uint32_t smem_to_u32(const void* p){
    uint32_t a;
    asm("{ .reg .u64 t; cvta.to.shared.u64 t, %1; cvt.u32.u64 %0, t; }" : "=r"(a) : "l"(p));
    return a;
}
#define CP_ASYNC16(dst, src) \
    asm volatile("cp.async.cg.shared.global [%0], [%1], 16;" :: "r"(dst), "l"(src))
#define CP_COMMIT() asm volatile("cp.async.commit_group;" ::: "memory")
#define CP_WAIT0()  asm volatile("cp.async.wait_group 0;" ::: "memory")

#define LDSM_X4(r, addr) \
    asm volatile("ldmatrix.sync.aligned.m8n8.x4.shared.b16 {%0,%1,%2,%3}, [%4];" \
        : "=r"((r)[0]),"=r"((r)[1]),"=r"((r)[2]),"=r"((r)[3]) : "r"(addr))
#define LDSM_X4_T(r, addr) \
    asm volatile("ldmatrix.sync.aligned.m8n8.x4.trans.shared.b16 {%0,%1,%2,%3}, [%4];" \
        : "=r"((r)[0]),"=r"((r)[1]),"=r"((r)[2]),"=r"((r)[3]) : "r"(addr))

#define MMA_BF16(c, a, b0, b1) \
    asm volatile("mma.sync.aligned.m16n8k16.row.col.f32.bf16.bf16.f32 " \
        "{%0,%1,%2,%3},{%4,%5,%6,%7},{%8,%9},{%0,%1,%2,%3};" \
        : "+f"((c)[0]),"+f"((c)[1]),"+f"((c)[2]),"+f"((c)[3]) \
        : "r"((a)[0]),"r"((a)[1]),"r"((a)[2]),"r"((a)[3]), "r"(b0),"r"(b1))

__device__ __forceinline__ uint32_t cvt_bf16x2(float lo, float hi){
    uint32_t d;
    asm("cvt.rn.bf16x2.f32 %0, %1, %2;" : "=r"(d) : "f"(hi), "f"(lo));
    return d;
}
__device__ __forceinline__ void split_pair(float x, float y, uint32_t& h2, uint32_t& l2){
    h2 = cvt_bf16x2(x, y);
    float xh = __int_as_float(h2 << 16);
    float yh = __int_as_float(h2 & 0xFFFF0000u);
    l2 = cvt_bf16x2(x - xh, y - yh);
}
// fast e^x on FMA/ALU pipes (avoids MUFU). valid for x <= 0, clamps below -87.
__device__ __forceinline__ float fast_exp(float x){
    x = fmaxf(x, -87.0f);
    float y = x * 1.4426950408889634f;
    float r = __fadd_rn(y, 12582912.0f);
    float f = y - __fadd_rn(r, -12582912.0f);
    float p = 1.5403530e-4f;
    p = __fmaf_rn(p, f, 1.3333558e-3f);
    p = __fmaf_rn(p, f, 9.6181291e-3f);
    p = __fmaf_rn(p, f, 5.5504109e-2f);
    p = __fmaf_rn(p, f, 2.4022651e-1f);
    p = __fmaf_rn(p, f, 6.9314718e-1f);
    p = __fmaf_rn(p, f, 1.0f);
    int n = __float_as_int(r) - 0x4B400000;
    return __int_as_float(__float_as_int(p) + (n << 23));
}

// ---------------- rope tables ----------------------------------------------
__global__ void rope_tables_kernel(){
    int idx = blockIdx.x * blockDim.x + threadIdx.x;
    if (idx >= S_*64) return;
    int s = idx >> 6, j = idx & 63;
    double inv = pow(500000.0, -((double)j)/64.0);
    float ang = (float)s * (float)inv;
    g_cos[idx] = (float)cos((double)ang);
    g_sin[idx] = (float)sin((double)ang);
}

// ---------------- fp32 -> bf16 hi/lo split ----------------------------------
__global__ void split_kernel(const float* __restrict__ src, int n, int dsel){
    __nv_bfloat16 *dH, *dL;
    switch (dsel){
        case 0: dH = g_hsH; dL = g_hsL; break;
        case 1: dH = g_WqH; dL = g_WqL; break;
        case 2: dH = g_WkH; dL = g_WkL; break;
        case 3: dH = g_WvH; dL = g_WvL; break;
        default:dH = g_WoH; dL = g_WoL; break;
    }
    int i = (blockIdx.x * blockDim.x + threadIdx.x) << 2;
    if (i >= n) return;
    float4 v = *(const float4*)(src + i);
    uint32_t h0, l0, h1, l1;
    split_pair(v.x, v.y, h0, l0);
    split_pair(v.z, v.w, h1, l1);
    *(uint32_t*)(dH + i)     = h0;
    *(uint32_t*)(dH + i + 2) = h1;
    *(uint32_t*)(dL + i)     = l0;
    *(uint32_t*)(dL + i + 2) = l1;
}

// ---------------- RoPE + scale + bf16 split (Q and K) ------------------------
__global__ void rope_convert_kernel(int which, int rows){
    int idx = blockIdx.x * blockDim.x + threadIdx.x;
    if (idx >= (rows << 6)) return;
    int r = idx >> 6, j = idx & 63;
    int s = r & (S_ - 1);
    const float* X = which ? g_K : g_Q;
    float c  = g_cos[(s << 6) + j];
    float sn = g_sin[(s << 6) + j];
    float x1 = X[((size_t)r << 7) + j], x2 = X[((size_t)r << 7) + j + 64];
    float y1 = x1 * c - x2 * sn;
    float y2 = x2 * c + x1 * sn;
    if (!which){ y1 *= 0.08838834764831845f; y2 *= 0.08838834764831845f; }
    __nv_bfloat16 *dH = which ? g_KbH : g_QbH;
    __nv_bfloat16 *dL = which ? g_KbL : g_QbL;
    __nv_bfloat16 h1b = __float2bfloat16(y1);
    __nv_bfloat16 h2b = __float2bfloat16(y2);
    dH[((size_t)r << 7) + j]      = h1b;
    dH[((size_t)r << 7) + j + 64] = h2b;
    dL[((size_t)r << 7) + j]      = __float2bfloat16(y1 - __bfloat162float(h1b));
    dL[((size_t)r << 7) + j + 64] = __float2bfloat16(y2 - __bfloat162float(h2b));
}

// ---------------- HMMA GEMM: C[M,N] = A[M,K]*B[N,K]^T, bf16 3-pass split ----
// BM=128 BN=128 BK=32; 8 warps (4x2); 2-stage cp.async; 2 CTAs/SM.
#define BK_      32
#define ROWB     80
#define MATB     (128*ROWB)             // 10240
#define STGB     (4*MATB)               // 40960
#define GSMEM    (2*STGB)               // 81920
#define KTILES   (H_/BK_)               // 128

__device__ __forceinline__ void hmma_load_stage(
    uint32_t sb, int s, const __nv_bfloat16* AH, const __nv_bfloat16* AL,
    const __nv_bfloat16* BH, const __nv_bfloat16* BL,
    int M0, int N0, int kt, int tid)
{
    uint32_t base = sb + s*STGB;
    #pragma unroll
    for (int i = 0; i < 2; ++i){
        int c = tid + (i << 8);
        int row = c >> 2, ch = c & 3;
        uint32_t soff = row*ROWB + (ch << 4);
        size_t ga = (size_t)(M0 + row)*H_ + kt*BK_ + (ch << 3);
        size_t gb = (size_t)(N0 + row)*H_ + kt*BK_ + (ch << 3);
        CP_ASYNC16(base + soff,          AH + ga);
        CP_ASYNC16(base + MATB + soff,   AL + ga);
        CP_ASYNC16(base + 2*MATB + soff, BH + gb);
        CP_ASYNC16(base + 3*MATB + soff, BL + gb);
    }
}

__global__ __launch_bounds__(256, 2)
void gemm_hmma_kernel(float* __restrict__ Cout, int asel, int bsel, int dest, int nheads)
{
    extern __shared__ char smem[];
    uint32_t sb = smem_to_u32(smem);
    const int tid = threadIdx.x;
    const int wid = tid >> 5, lane = tid & 31;
    const int wm = wid & 3, wn = wid >> 2;
    const int M0 = blockIdx.y << 7, N0 = blockIdx.x << 7;

    const __nv_bfloat16 *AH = asel ? g_OH : g_hsH;
    const __nv_bfloat16 *AL = asel ? g_OL : g_hsL;
    const __nv_bfloat16 *BH, *BL;
    switch (bsel){
        case 0: BH = g_WqH; BL = g_WqL; break;
        case 1: BH = g_WkH; BL = g_WkL; break;
        case 2: BH = g_WvH; BL = g_WvL; break;
        default:BH = g_WoH; BL = g_WoL; break;
    }

    float acc[2][8][4];
    #pragma unroll
    for (int m = 0; m < 2; ++m)
        #pragma unroll
        for (int n = 0; n < 8; ++n)
            #pragma unroll
            for (int j = 0; j < 4; ++j) acc[m][n][j] = 0.f;

    hmma_load_stage(sb, 0, AH, AL, BH, BL, M0, N0, 0, tid); CP_COMMIT();

    const uint32_t aRow = (uint32_t)(wm*32 + (lane & 15));
    const uint32_t aColB = (uint32_t)(((lane >> 4) << 3) * 2);
    const uint32_t bRow = (uint32_t)(wn*64 + ((lane & 7) | ((lane & 16) >> 1)));
    const uint32_t bColB = (uint32_t)((((lane >> 3) & 1) << 3) * 2);

    #pragma unroll 1
    for (int kt = 0; kt < KTILES; ++kt){
        const int s = kt & 1;
        CP_WAIT0();
        __syncthreads();
        if (kt + 1 < KTILES){
            hmma_load_stage(sb, s^1, AH, AL, BH, BL, M0, N0, kt + 1, tid);
            CP_COMMIT();
        }

        const uint32_t stA = sb + s*STGB;
        const uint32_t stB = stA + 2*MATB;
        #pragma unroll
        for (int ks = 0; ks < 2; ++ks){
            const uint32_t kB = (uint32_t)(ks << 5);
            uint32_t aHr[2][4], aLr[2][4];
            #pragma unroll
            for (int mm = 0; mm < 2; ++mm){
                uint32_t off = (aRow + mm*16)*ROWB + kB + aColB;
                LDSM_X4(aHr[mm], stA + off);
                LDSM_X4(aLr[mm], stA + MATB + off);
            }
            #pragma unroll
            for (int g = 0; g < 4; ++g){
                uint32_t bH[4], bL[4];
                uint32_t off = (bRow + g*16)*ROWB + kB + bColB;
                LDSM_X4(bH, stB + off);
                LDSM_X4(bL, stB + MATB + off);
                #pragma unroll
                for (int mm = 0; mm < 2; ++mm){
                    MMA_BF16(acc[mm][2*g],   aHr[mm], bH[0], bH[1]);
                    MMA_BF16(acc[mm][2*g],   aHr[mm], bL[0], bL[1]);
                    MMA_BF16(acc[mm][2*g],   aLr[mm], bH[0], bH[1]);
                    MMA_BF16(acc[mm][2*g+1], aHr[mm], bH[2], bH[3]);
                    MMA_BF16(acc[mm][2*g+1], aHr[mm], bL[2], bL[3]);
                    MMA_BF16(acc[mm][2*g+1], aLr[mm], bH[2], bH[3]);
                }
            }
        }
    }

    // ---- epilogue ----
    const int rbase = M0 + wm*32 + (lane >> 2);
    const int cbase = wn*64 + (lane & 3)*2;
    #pragma unroll
    for (int mm = 0; mm < 2; ++mm){
        #pragma unroll
        for (int half = 0; half < 2; ++half){
            int r = rbase + mm*16 + half*8;
            #pragma unroll
            for (int nn = 0; nn < 8; ++nn){
                float vx = acc[mm][nn][half*2];
                float vy = acc[mm][nn][half*2 + 1];
                if (dest == 3){
                    float2 v; v.x = vx; v.y = vy;
                    *(float2*)(Cout + (size_t)r*H_ + N0 + cbase + nn*8) = v;
                } else {
                    int bb = r >> 11, ss = r & (S_ - 1);
                    size_t idx = (((size_t)bb*nheads + blockIdx.x)*S_ + ss)*HD_ + cbase + nn*8;
                    if (dest == 2){
                        uint32_t h2, l2;
                        split_pair(vx, vy, h2, l2);
                        *(uint32_t*)(g_VbH + idx) = h2;
                        *(uint32_t*)(g_VbL + idx) = l2;
                    } else {
                        float2 v; v.x = vx; v.y = vy;
                        float* Cp = (dest == 0) ? g_Q : g_K;
                        *(float2*)(Cp + idx) = v;
                    }
                }
            }
        }
    }
}

// ---------------- HMMA flash attention --------------------------------------
#define AROWB 272
#define AQMAT (128*AROWB)
#define AKMAT (64*AROWB)
#define ASTGB (4*AKMAT)
#define ASMEM (2*AQMAT + 2*ASTGB)

__device__ __forceinline__ void attn_load_kv(
    uint32_t st, const __nv_bfloat16* KH, const __nv_bfloat16* KL,
    const __nv_bfloat16* VH, const __nv_bfloat16* VL, int key0, int tid)
{
    #pragma unroll
    for (int i = 0; i < 16; ++i){
        int c = tid + (i << 8);
        int mat = c >> 10;
        int cc = c & 1023;
        int row = cc >> 4, ch = cc & 15;
        uint32_t dst = st + mat*AKMAT + row*AROWB + (ch << 4);
        const __nv_bfloat16* src = (mat == 0) ? KH : (mat == 1) ? KL : (mat == 2) ? VH : VL;
        CP_ASYNC16(dst, src + (size_t)(key0 + row)*HD_ + (ch << 3));
    }
}

__global__ __launch_bounds__(256, 1)
void attn_mma_kernel(){
    extern __shared__ char smem[];
    uint32_t sb = smem_to_u32(smem);
    const int tid = threadIdx.x;
    const int wid = tid >> 5, lane = tid & 31;
    const int qb = blockIdx.x, h = blockIdx.y, b = blockIdx.z;
    const int g = h >> 2;

    const __nv_bfloat16* QHg = g_QbH + (((size_t)b*NH_ + h)*S_ + (size_t)qb*128)*HD_;
    const __nv_bfloat16* QLg = g_QbL + (((size_t)b*NH_ + h)*S_ + (size_t)qb*128)*HD_;
    const __nv_bfloat16* KHg = g_KbH + ((size_t)b*NKV_ + g)*S_*HD_;
    const __nv_bfloat16* KLg = g_KbL + ((size_t)b*NKV_ + g)*S_*HD_;
    const __nv_bfloat16* VHg = g_VbH + ((size_t)b*NKV_ + g)*S_*HD_;
    const __nv_bfloat16* VLg = g_VbL + ((size_t)b*NKV_ + g)*S_*HD_;

    const uint32_t QH0 = sb, QL0 = sb + AQMAT;

    #pragma unroll
    for (int i = 0; i < 16; ++i){
        int c = tid + (i << 8);
        int mat = c >> 11;
        int cc = c & 2047;
        int row = cc >> 4, ch = cc & 15;
        uint32_t dst = (mat ? QL0 : QH0) + row*AROWB + (ch << 4);
        const __nv_bfloat16* src = mat ? QLg : QHg;
        CP_ASYNC16(dst, src + (size_t)row*HD_ + (ch << 3));
    }
    attn_load_kv(sb + 2*AQMAT, KHg, KLg, VHg, VLg, 0, tid);
    CP_COMMIT();

    float m0 = -1e30f, m1 = -1e30f, l0 = 0.f, l1 = 0.f;
    float O[16][4];
    #pragma unroll
    for (int nt = 0; nt < 16; ++nt)
        #pragma unroll
        for (int j = 0; j < 4; ++j) O[nt][j] = 0.f;

    const uint32_t aOff  = (uint32_t)(wid*16 + (lane & 15))*AROWB + ((lane >> 4) << 4);
    const uint32_t bOffK = (uint32_t)((lane & 7) | ((lane & 16) >> 1))*AROWB + (((lane >> 3) & 1) << 4);
    const uint32_t vOff  = (uint32_t)((lane & 7) + (lane & 8))*AROWB + ((lane >> 4) << 4);

    #pragma unroll 1
    for (int kb = 0; kb < S_/64; ++kb){
        const int s = kb & 1;
        const uint32_t KH = sb + 2*AQMAT + s*ASTGB;
        const uint32_t KL = KH + AKMAT, VH = KH + 2*AKMAT, VL = KH + 3*AKMAT;

        CP_WAIT0();
        __syncthreads();
        if (kb + 1 < S_/64){
            attn_load_kv(sb + 2*AQMAT + (s^1)*ASTGB, KHg, KLg, VHg, VLg, (kb+1)*64, tid);
            CP_COMMIT();
        }

        // ---- S = Q K^T (3-pass) ----
        float Sa[8][4];
        #pragma unroll
        for (int nt = 0; nt < 8; ++nt)
            #pragma unroll
            for (int j = 0; j < 4; ++j) Sa[nt][j] = 0.f;

        #pragma unroll
        for (int ks = 0; ks < 8; ++ks){
            uint32_t aH[4], aL[4];
            LDSM_X4(aH, QH0 + aOff + ks*32);
            LDSM_X4(aL, QL0 + aOff + ks*32);
            #pragma unroll
            for (int gi = 0; gi < 4; ++gi){
                uint32_t bH[4], bL[4];
                uint32_t off = bOffK + gi*(16*AROWB) + ks*32;
                LDSM_X4(bH, KH + off);
                LDSM_X4(bL, KL + off);
                MMA_BF16(Sa[2*gi],   aH, bH[0], bH[1]);
                MMA_BF16(Sa[2*gi],   aH, bL[0], bL[1]);
                MMA_BF16(Sa[2*gi],   aL, bH[0], bH[1]);
                MMA_BF16(Sa[2*gi+1], aH, bH[2], bH[3]);
                MMA_BF16(Sa[2*gi+1], aH, bL[2], bL[3]);
                MMA_BF16(Sa[2*gi+1], aL, bH[2], bH[3]);
            }
        }

        // ---- online softmax ----
        float mb0 = -1e30f, mb1 = -1e30f;
        #pragma unroll
        for (int nt = 0; nt < 8; ++nt){
            mb0 = fmaxf(mb0, fmaxf(Sa[nt][0], Sa[nt][1]));
            mb1 = fmaxf(mb1, fmaxf(Sa[nt][2], Sa[nt][3]));
        }
        mb0 = fmaxf(mb0, __shfl_xor_sync(0xffffffffu, mb0, 1));
        mb0 = fmaxf(mb0, __shfl_xor_sync(0xffffffffu, mb0, 2));
        mb1 = fmaxf(mb1, __shfl_xor_sync(0xffffffffu, mb1, 1));
        mb1 = fmaxf(mb1, __shfl_xor_sync(0xffffffffu, mb1, 2));
        float m0n = fmaxf(m0, mb0), m1n = fmaxf(m1, mb1);
        float corr0 = fast_exp(m0 - m0n), corr1 = fast_exp(m1 - m1n);
        m0 = m0n; m1 = m1n;

        float ls0 = 0.f, ls1 = 0.f;
        #pragma unroll
        for (int nt = 0; nt < 8; ++nt){
            Sa[nt][0] = fast_exp(Sa[nt][0] - m0);
            Sa[nt][1] = fast_exp(Sa[nt][1] - m0);
            Sa[nt][2] = fast_exp(Sa[nt][2] - m1);
            Sa[nt][3] = fast_exp(Sa[nt][3] - m1);
            ls0 += Sa[nt][0] + Sa[nt][1];
            ls1 += Sa[nt][2] + Sa[nt][3];
        }
        ls0 += __shfl_xor_sync(0xffffffffu, ls0, 1);
        ls0 += __shfl_xor_sync(0xffffffffu, ls0, 2);
        ls1 += __shfl_xor_sync(0xffffffffu, ls1, 1);
        ls1 += __shfl_xor_sync(0xffffffffu, ls1, 2);
        l0 = l0*corr0 + ls0;
        l1 = l1*corr1 + ls1;

        #pragma unroll
        for (int nt = 0; nt < 16; ++nt){
            O[nt][0] *= corr0; O[nt][1] *= corr0;
            O[nt][2] *= corr1; O[nt][3] *= corr1;
        }

        // ---- P -> A fragments (bf16 hi/lo) ----
        uint32_t aPh[4][4], aPl[4][4];
        #pragma unroll
        for (int kt = 0; kt < 4; ++kt){
            split_pair(Sa[2*kt][0],   Sa[2*kt][1],   aPh[kt][0], aPl[kt][0]);
            split_pair(Sa[2*kt][2],   Sa[2*kt][3],   aPh[kt][1], aPl[kt][1]);
            split_pair(Sa[2*kt+1][0], Sa[2*kt+1][1], aPh[kt][2], aPl[kt][2]);
            split_pair(Sa[2*kt+1][2], Sa[2*kt+1][3], aPh[kt][3], aPl[kt][3]);
        }

        // ---- O += P V (3-pass, V via ldmatrix.trans) ----
        #pragma unroll
        for (int kt = 0; kt < 4; ++kt){
            #pragma unroll
            for (int dp = 0; dp < 8; ++dp){
                uint32_t bVh[4], bVl[4];
                uint32_t off = vOff + kt*(16*AROWB) + dp*32;
                LDSM_X4_T(bVh, VH + off);
                LDSM_X4_T(bVl, VL + off);
                MMA_BF16(O[2*dp],   aPh[kt], bVh[0], bVh[1]);
                MMA_BF16(O[2*dp],   aPl[kt], bVh[0], bVh[1]);
                MMA_BF16(O[2*dp],   aPh[kt], bVl[0], bVl[1]);
                MMA_BF16(O[2*dp+1], aPh[kt], bVh[2], bVh[3]);
                MMA_BF16(O[2*dp+1], aPl[kt], bVh[2], bVh[3]);
                MMA_BF16(O[2*dp+1], aPh[kt], bVl[2], bVl[3]);
            }
        }
    }

    // ---- epilogue ----
    const float inv0 = 1.0f / l0, inv1 = 1.0f / l1;
    const int s0 = qb*128 + wid*16 + (lane >> 2);
    const size_t ob = (size_t)b*S_*H_ + (size_t)h*HD_;
    #pragma unroll
    for (int nt = 0; nt < 16; ++nt){
        int d = nt*8 + (lane & 3)*2;
        uint32_t h2, l2;
        split_pair(O[nt][0]*inv0, O[nt][1]*inv0, h2, l2);
        size_t idx0 = ob + (size_t)s0*H_ + d;
        *(uint32_t*)(g_OH + idx0) = h2;
        *(uint32_t*)(g_OL + idx0) = l2;
        split_pair(O[nt][2]*inv1, O[nt][3]*inv1, h2, l2);
        size_t idx1 = ob + (size_t)(s0 + 8)*H_ + d;
        *(uint32_t*)(g_OH + idx1) = h2;
        *(uint32_t*)(g_OL + idx1) = l2;
    }
}

// ---------------- launch ----------------------------------------------------
extern "C" void kernel_launch(void* const* d_in, const int* in_sizes, int n_in,
                              void* d_out, int out_size)
{
    const float* hs = (const float*)d_in[0];
    const float* Wq = (const float*)d_in[1];
    const float* Wk = (const float*)d_in[2];
    const float* Wv = (const float*)d_in[3];
    const float* Wo = (const float*)d_in[4];
    float* out = (float*)d_out;

    rope_tables_kernel<<<(S_*64 + 255)/256, 256>>>();

    split_kernel<<<(TOK*H_/4 + 255)/256, 256>>>(hs, TOK*H_, 0);
    split_kernel<<<(NH_*HD_*H_/4 + 255)/256, 256>>>(Wq, NH_*HD_*H_, 1);
    split_kernel<<<(NKV_*HD_*H_/4 + 255)/256, 256>>>(Wk, NKV_*HD_*H_, 2);
    split_kernel<<<(NKV_*HD_*H_/4 + 255)/256, 256>>>(Wv, NKV_*HD_*H_, 3);
    split_kernel<<<(H_*H_/4 + 255)/256, 256>>>(Wo, H_*H_, 4);

    cudaFuncSetAttribute(gemm_hmma_kernel, cudaFuncAttributeMaxDynamicSharedMemorySize, GSMEM);

    gemm_hmma_kernel<<<dim3(32, 32), 256, GSMEM>>>(nullptr, 0, 0, 0, NH_);
    gemm_hmma_kernel<<<dim3(8,  32), 256, GSMEM>>>(nullptr, 0, 1, 1, NKV_);
    gemm_hmma_kernel<<<dim3(8,  32), 256, GSMEM>>>(nullptr, 0, 2, 2, NKV_);

    rope_convert_kernel<<<(B_*NH_*S_*64)/256,  256>>>(0, B_*NH_*S_);
    rope_convert_kernel<<<(B_*NKV_*S_*64)/256, 256>>>(1, B_*NKV_*S_);

    cudaFuncSetAttribute(attn_mma_kernel, cudaFuncAttributeMaxDynamicSharedMemorySize, ASMEM);
    attn_mma_kernel<<<dim3(S_/128, NH_, B_), 256, ASMEM>>>();

    gemm_hmma_kernel<<<dim3(32, 32), 256, GSMEM>>>(out, 1, 3, 3, 0);
}

// round 6
// speedup vs baseline: 4.2024x; 1.4145x over previous
#include <cuda_runtime.h>
#include <cuda_fp16.h>
#include <math.h>
#include <stdint.h>

#define B_   2
#define S_   2048
#define H_   4096
#define NH_  32
#define NKV_ 8
#define HD_  128
#define TOK  (B_*S_)        // 4096

// ---------------- scratch (static device globals; no allocation) ----------
__device__ float g_Q[(size_t)B_*NH_*S_*HD_];
__device__ float g_K[(size_t)B_*NKV_*S_*HD_];
__device__ float g_cos[S_*64];
__device__ float g_sin[S_*64];

// fp16 operands
__device__ __half g_hsH[(size_t)TOK*H_], g_hsL[(size_t)TOK*H_];
__device__ __half g_Wq[(size_t)NH_*HD_*H_];
__device__ __half g_Wk[(size_t)NKV_*HD_*H_];
__device__ __half g_Wv[(size_t)NKV_*HD_*H_];
__device__ __half g_Wo[(size_t)H_*H_];
__device__ __half g_OH[(size_t)TOK*H_], g_OL[(size_t)TOK*H_];

// attention operands (fp16; RoPE and scale pre-applied)
__device__ __half g_QbH[(size_t)B_*NH_*S_*HD_], g_QbL[(size_t)B_*NH_*S_*HD_];
__device__ __half g_Kb[(size_t)B_*NKV_*S_*HD_];
__device__ __half g_Vb[(size_t)B_*NKV_*S_*HD_];

// ---------------- helpers ----------------------------------------------------
__device__ __forceinline__ uint32_t smem_to_u32(const void* p){
    uint32_t a;
    asm("{ .reg .u64 t; cvta.to.shared.u64 t, %1; cvt.u32.u64 %0, t; }" : "=r"(a) : "l"(p));
    return a;
}
#define CP_ASYNC16(dst, src) \
    asm volatile("cp.async.cg.shared.global [%0], [%1], 16;" :: "r"(dst), "l"(src))
#define CP_COMMIT() asm volatile("cp.async.commit_group;" ::: "memory")
#define CP_WAIT0()  asm volatile("cp.async.wait_group 0;" ::: "memory")

#define LDSM_X4(r, addr) \
    asm volatile("ldmatrix.sync.aligned.m8n8.x4.shared.b16 {%0,%1,%2,%3}, [%4];" \
        : "=r"((r)[0]),"=r"((r)[1]),"=r"((r)[2]),"=r"((r)[3]) : "r"(addr))
#define LDSM_X4_T(r, addr) \
    asm volatile("ldmatrix.sync.aligned.m8n8.x4.trans.shared.b16 {%0,%1,%2,%3}, [%4];" \
        : "=r"((r)[0]),"=r"((r)[1]),"=r"((r)[2]),"=r"((r)[3]) : "r"(addr))

#define MMA_F16(c, a, b0, b1) \
    asm volatile("mma.sync.aligned.m16n8k16.row.col.f32.f16.f16.f32 " \
        "{%0,%1,%2,%3},{%4,%5,%6,%7},{%8,%9},{%0,%1,%2,%3};" \
        : "+f"((c)[0]),"+f"((c)[1]),"+f"((c)[2]),"+f"((c)[3]) \
        : "r"((a)[0]),"r"((a)[1]),"r"((a)[2]),"r"((a)[3]), "r"(b0),"r"(b1))

__device__ __forceinline__ uint32_t f2h2(float x, float y){
    __half2 h = __floats2half2_rn(x, y);
    return *(uint32_t*)&h;
}
__device__ __forceinline__ void split_pair_h(float x, float y, uint32_t& h2, uint32_t& l2){
    h2 = f2h2(x, y);
    float2 f = __half22float2(*(__half2*)&h2);
    l2 = f2h2(x - f.x, y - f.y);
}
// fast e^x on FMA/ALU pipes. valid for x <= 0, clamps below -87.
__device__ __forceinline__ float fast_exp(float x){
    x = fmaxf(x, -87.0f);
    float y = x * 1.4426950408889634f;
    float r = __fadd_rn(y, 12582912.0f);
    float f = y - __fadd_rn(r, -12582912.0f);
    float p = 1.5403530e-4f;
    p = __fmaf_rn(p, f, 1.3333558e-3f);
    p = __fmaf_rn(p, f, 9.6181291e-3f);
    p = __fmaf_rn(p, f, 5.5504109e-2f);
    p = __fmaf_rn(p, f, 2.4022651e-1f);
    p = __fmaf_rn(p, f, 6.9314718e-1f);
    p = __fmaf_rn(p, f, 1.0f);
    int n = __float_as_int(r) - 0x4B400000;
    return __int_as_float(__float_as_int(p) + (n << 23));
}

// ---------------- rope tables ----------------------------------------------
__global__ void rope_tables_kernel(){
    int idx = blockIdx.x * blockDim.x + threadIdx.x;
    if (idx >= S_*64) return;
    int s = idx >> 6, j = idx & 63;
    double inv = pow(500000.0, -((double)j)/64.0);
    float ang = (float)s * (float)inv;
    g_cos[idx] = (float)cos((double)ang);
    g_sin[idx] = (float)sin((double)ang);
}

// ---------------- fp32 -> fp16 hi/lo split (hidden states) -------------------
__global__ void split_hs_kernel(const float* __restrict__ src, int n){
    int i = (blockIdx.x * blockDim.x + threadIdx.x) << 2;
    if (i >= n) return;
    float4 v = *(const float4*)(src + i);
    uint32_t h0, l0, h1, l1;
    split_pair_h(v.x, v.y, h0, l0);
    split_pair_h(v.z, v.w, h1, l1);
    *(uint32_t*)(g_hsH + i)     = h0;
    *(uint32_t*)(g_hsH + i + 2) = h1;
    *(uint32_t*)(g_hsL + i)     = l0;
    *(uint32_t*)(g_hsL + i + 2) = l1;
}

// ---------------- fp32 -> fp16 convert (weights) ------------------------------
__global__ void convert_h_kernel(const float* __restrict__ src, int n, int dsel){
    __half* d;
    switch (dsel){
        case 1: d = g_Wq; break;
        case 2: d = g_Wk; break;
        case 3: d = g_Wv; break;
        default:d = g_Wo; break;
    }
    int i = (blockIdx.x * blockDim.x + threadIdx.x) << 2;
    if (i >= n) return;
    float4 v = *(const float4*)(src + i);
    *(uint32_t*)(d + i)     = f2h2(v.x, v.y);
    *(uint32_t*)(d + i + 2) = f2h2(v.z, v.w);
}

// ---------------- RoPE + scale + fp16 (Q hi/lo split; K single) --------------
__global__ void rope_convert_kernel(int which, int rows){
    int idx = blockIdx.x * blockDim.x + threadIdx.x;
    if (idx >= (rows << 6)) return;
    int r = idx >> 6, j = idx & 63;
    int s = r & (S_ - 1);
    const float* X = which ? g_K : g_Q;
    float c  = g_cos[(s << 6) + j];
    float sn = g_sin[(s << 6) + j];
    float x1 = X[((size_t)r << 7) + j], x2 = X[((size_t)r << 7) + j + 64];
    float y1 = x1 * c - x2 * sn;
    float y2 = x2 * c + x1 * sn;
    if (which){
        g_Kb[((size_t)r << 7) + j]      = __float2half_rn(y1);
        g_Kb[((size_t)r << 7) + j + 64] = __float2half_rn(y2);
    } else {
        y1 *= 0.08838834764831845f; y2 *= 0.08838834764831845f;
        __half h1 = __float2half_rn(y1), h2 = __float2half_rn(y2);
        g_QbH[((size_t)r << 7) + j]      = h1;
        g_QbH[((size_t)r << 7) + j + 64] = h2;
        g_QbL[((size_t)r << 7) + j]      = __float2half_rn(y1 - __half2float(h1));
        g_QbL[((size_t)r << 7) + j + 64] = __float2half_rn(y2 - __half2float(h2));
    }
}

// ---------------- HMMA GEMM: C[M,N] = A[M,K]*B[N,K]^T, fp16 2-pass ----------
// BM=128 BN=128 BK=32; 8 warps (4x2); 2-stage cp.async; 2 CTAs/SM.
#define BK_      32
#define ROWB     80
#define MATB     (128*ROWB)             // 10240
#define STGB     (3*MATB)               // 30720 (AH, AL, BH)
#define GSMEM    (2*STGB)               // 61440
#define KTILES   (H_/BK_)               // 128

__device__ __forceinline__ void hmma_load_stage(
    uint32_t sb, int s, const __half* AH, const __half* AL, const __half* BH,
    int M0, int N0, int kt, int tid)
{
    uint32_t base = sb + s*STGB;
    #pragma unroll
    for (int i = 0; i < 6; ++i){
        int c = tid + (i << 8);          // 0..1535
        int mat = c >> 9;                // 0=AH 1=AL 2=BH
        int cc = c & 511;
        int row = cc >> 2, ch = cc & 3;
        uint32_t soff = (uint32_t)mat*MATB + row*ROWB + (ch << 4);
        const __half* src = (mat == 0) ? AH : (mat == 1) ? AL : BH;
        int base_row = (mat == 2) ? N0 : M0;
        CP_ASYNC16(base + soff, src + (size_t)(base_row + row)*H_ + kt*BK_ + (ch << 3));
    }
}

__global__ __launch_bounds__(256, 2)
void gemm_hmma_kernel(float* __restrict__ Cout, int asel, int bsel, int dest, int nheads)
{
    extern __shared__ char smem[];
    uint32_t sb = smem_to_u32(smem);
    const int tid = threadIdx.x;
    const int wid = tid >> 5, lane = tid & 31;
    const int wm = wid & 3, wn = wid >> 2;
    const int M0 = blockIdx.y << 7, N0 = blockIdx.x << 7;

    const __half *AH = asel ? g_OH : g_hsH;
    const __half *AL = asel ? g_OL : g_hsL;
    const __half *BH;
    switch (bsel){
        case 0: BH = g_Wq; break;
        case 1: BH = g_Wk; break;
        case 2: BH = g_Wv; break;
        default:BH = g_Wo; break;
    }

    float acc[2][8][4];
    #pragma unroll
    for (int m = 0; m < 2; ++m)
        #pragma unroll
        for (int n = 0; n < 8; ++n)
            #pragma unroll
            for (int j = 0; j < 4; ++j) acc[m][n][j] = 0.f;

    hmma_load_stage(sb, 0, AH, AL, BH, M0, N0, 0, tid); CP_COMMIT();

    const uint32_t aRow = (uint32_t)(wm*32 + (lane & 15));
    const uint32_t aColB = (uint32_t)(((lane >> 4) << 3) * 2);
    const uint32_t bRow = (uint32_t)(wn*64 + ((lane & 7) | ((lane & 16) >> 1)));
    const uint32_t bColB = (uint32_t)((((lane >> 3) & 1) << 3) * 2);

    #pragma unroll 1
    for (int kt = 0; kt < KTILES; ++kt){
        const int s = kt & 1;
        CP_WAIT0();
        __syncthreads();
        if (kt + 1 < KTILES){
            hmma_load_stage(sb, s^1, AH, AL, BH, M0, N0, kt + 1, tid);
            CP_COMMIT();
        }

        const uint32_t stA = sb + s*STGB;
        const uint32_t stB = stA + 2*MATB;
        #pragma unroll
        for (int ks = 0; ks < 2; ++ks){
            const uint32_t kB = (uint32_t)(ks << 5);
            uint32_t aHr[2][4], aLr[2][4];
            #pragma unroll
            for (int mm = 0; mm < 2; ++mm){
                uint32_t off = (aRow + mm*16)*ROWB + kB + aColB;
                LDSM_X4(aHr[mm], stA + off);
                LDSM_X4(aLr[mm], stA + MATB + off);
            }
            #pragma unroll
            for (int g = 0; g < 4; ++g){
                uint32_t bH[4];
                uint32_t off = (bRow + g*16)*ROWB + kB + bColB;
                LDSM_X4(bH, stB + off);
                #pragma unroll
                for (int mm = 0; mm < 2; ++mm){
                    MMA_F16(acc[mm][2*g],   aHr[mm], bH[0], bH[1]);
                    MMA_F16(acc[mm][2*g],   aLr[mm], bH[0], bH[1]);
                    MMA_F16(acc[mm][2*g+1], aHr[mm], bH[2], bH[3]);
                    MMA_F16(acc[mm][2*g+1], aLr[mm], bH[2], bH[3]);
                }
            }
        }
    }

    // ---- epilogue ----
    const int rbase = M0 + wm*32 + (lane >> 2);
    const int cbase = wn*64 + (lane & 3)*2;
    #pragma unroll
    for (int mm = 0; mm < 2; ++mm){
        #pragma unroll
        for (int half = 0; half < 2; ++half){
            int r = rbase + mm*16 + half*8;
            #pragma unroll
            for (int nn = 0; nn < 8; ++nn){
                float vx = acc[mm][nn][half*2];
                float vy = acc[mm][nn][half*2 + 1];
                if (dest == 3){
                    float2 v; v.x = vx; v.y = vy;
                    *(float2*)(Cout + (size_t)r*H_ + N0 + cbase + nn*8) = v;
                } else {
                    int bb = r >> 11, ss = r & (S_ - 1);
                    size_t idx = (((size_t)bb*nheads + blockIdx.x)*S_ + ss)*HD_ + cbase + nn*8;
                    if (dest == 2){
                        *(uint32_t*)(g_Vb + idx) = f2h2(vx, vy);
                    } else {
                        float2 v; v.x = vx; v.y = vy;
                        float* Cp = (dest == 0) ? g_Q : g_K;
                        *(float2*)(Cp + idx) = v;
                    }
                }
            }
        }
    }
}

// ---------------- HMMA flash attention (fp16 2-pass) -------------------------
#define AROWB 272
#define AQMAT (128*AROWB)               // 34816
#define AKMAT (64*AROWB)                // 17408
#define ASTGB (2*AKMAT)                 // K + V = 34816
#define ASMEM (2*AQMAT + 2*ASTGB)       // 139264

__device__ __forceinline__ void attn_load_kv(
    uint32_t st, const __half* Kg, const __half* Vg, int key0, int tid)
{
    #pragma unroll
    for (int i = 0; i < 8; ++i){
        int c = tid + (i << 8);          // 0..2047
        int mat = c >> 10;               // 0=K 1=V
        int cc = c & 1023;
        int row = cc >> 4, ch = cc & 15;
        uint32_t dst = st + (uint32_t)mat*AKMAT + row*AROWB + (ch << 4);
        const __half* src = mat ? Vg : Kg;
        CP_ASYNC16(dst, src + (size_t)(key0 + row)*HD_ + (ch << 3));
    }
}

__global__ __launch_bounds__(256, 1)
void attn_mma_kernel(){
    extern __shared__ char smem[];
    uint32_t sb = smem_to_u32(smem);
    const int tid = threadIdx.x;
    const int wid = tid >> 5, lane = tid & 31;
    const int qb = blockIdx.x, h = blockIdx.y, b = blockIdx.z;
    const int g = h >> 2;

    const __half* QHg = g_QbH + (((size_t)b*NH_ + h)*S_ + (size_t)qb*128)*HD_;
    const __half* QLg = g_QbL + (((size_t)b*NH_ + h)*S_ + (size_t)qb*128)*HD_;
    const __half* Kg  = g_Kb + ((size_t)b*NKV_ + g)*S_*HD_;
    const __half* Vg  = g_Vb + ((size_t)b*NKV_ + g)*S_*HD_;

    const uint32_t QH0 = sb, QL0 = sb + AQMAT;

    #pragma unroll
    for (int i = 0; i < 16; ++i){
        int c = tid + (i << 8);
        int mat = c >> 11;
        int cc = c & 2047;
        int row = cc >> 4, ch = cc & 15;
        uint32_t dst = (mat ? QL0 : QH0) + row*AROWB + (ch << 4);
        const __half* src = mat ? QLg : QHg;
        CP_ASYNC16(dst, src + (size_t)row*HD_ + (ch << 3));
    }
    attn_load_kv(sb + 2*AQMAT, Kg, Vg, 0, tid);
    CP_COMMIT();

    float m0 = -1e30f, m1 = -1e30f, l0 = 0.f, l1 = 0.f;
    float O[16][4];
    #pragma unroll
    for (int nt = 0; nt < 16; ++nt)
        #pragma unroll
        for (int j = 0; j < 4; ++j) O[nt][j] = 0.f;

    const uint32_t aOff  = (uint32_t)(wid*16 + (lane & 15))*AROWB + ((lane >> 4) << 4);
    const uint32_t bOffK = (uint32_t)((lane & 7) | ((lane & 16) >> 1))*AROWB + (((lane >> 3) & 1) << 4);
    const uint32_t vOff  = (uint32_t)((lane & 7) + (lane & 8))*AROWB + ((lane >> 4) << 4);

    #pragma unroll 1
    for (int kb = 0; kb < S_/64; ++kb){
        const int s = kb & 1;
        const uint32_t Kst = sb + 2*AQMAT + s*ASTGB;
        const uint32_t Vst = Kst + AKMAT;

        CP_WAIT0();
        __syncthreads();
        if (kb + 1 < S_/64){
            attn_load_kv(sb + 2*AQMAT + (s^1)*ASTGB, Kg, Vg, (kb+1)*64, tid);
            CP_COMMIT();
        }

        // ---- S = Q K^T (2-pass fp16) ----
        float Sa[8][4];
        #pragma unroll
        for (int nt = 0; nt < 8; ++nt)
            #pragma unroll
            for (int j = 0; j < 4; ++j) Sa[nt][j] = 0.f;

        #pragma unroll
        for (int ks = 0; ks < 8; ++ks){
            uint32_t aH[4], aL[4];
            LDSM_X4(aH, QH0 + aOff + ks*32);
            LDSM_X4(aL, QL0 + aOff + ks*32);
            #pragma unroll
            for (int gi = 0; gi < 4; ++gi){
                uint32_t bK[4];
                LDSM_X4(bK, Kst + bOffK + gi*(16*AROWB) + ks*32);
                MMA_F16(Sa[2*gi],   aH, bK[0], bK[1]);
                MMA_F16(Sa[2*gi],   aL, bK[0], bK[1]);
                MMA_F16(Sa[2*gi+1], aH, bK[2], bK[3]);
                MMA_F16(Sa[2*gi+1], aL, bK[2], bK[3]);
            }
        }

        // ---- online softmax ----
        float mb0 = -1e30f, mb1 = -1e30f;
        #pragma unroll
        for (int nt = 0; nt < 8; ++nt){
            mb0 = fmaxf(mb0, fmaxf(Sa[nt][0], Sa[nt][1]));
            mb1 = fmaxf(mb1, fmaxf(Sa[nt][2], Sa[nt][3]));
        }
        mb0 = fmaxf(mb0, __shfl_xor_sync(0xffffffffu, mb0, 1));
        mb0 = fmaxf(mb0, __shfl_xor_sync(0xffffffffu, mb0, 2));
        mb1 = fmaxf(mb1, __shfl_xor_sync(0xffffffffu, mb1, 1));
        mb1 = fmaxf(mb1, __shfl_xor_sync(0xffffffffu, mb1, 2));
        float m0n = fmaxf(m0, mb0), m1n = fmaxf(m1, mb1);
        float corr0 = fast_exp(m0 - m0n), corr1 = fast_exp(m1 - m1n);
        m0 = m0n; m1 = m1n;

        float ls0 = 0.f, ls1 = 0.f;
        #pragma unroll
        for (int nt = 0; nt < 8; ++nt){
            Sa[nt][0] = fast_exp(Sa[nt][0] - m0);
            Sa[nt][1] = fast_exp(Sa[nt][1] - m0);
            Sa[nt][2] = fast_exp(Sa[nt][2] - m1);
            Sa[nt][3] = fast_exp(Sa[nt][3] - m1);
            ls0 += Sa[nt][0] + Sa[nt][1];
            ls1 += Sa[nt][2] + Sa[nt][3];
        }
        ls0 += __shfl_xor_sync(0xffffffffu, ls0, 1);
        ls0 += __shfl_xor_sync(0xffffffffu, ls0, 2);
        ls1 += __shfl_xor_sync(0xffffffffu, ls1, 1);
        ls1 += __shfl_xor_sync(0xffffffffu, ls1, 2);
        l0 = l0*corr0 + ls0;
        l1 = l1*corr1 + ls1;

        #pragma unroll
        for (int nt = 0; nt < 16; ++nt){
            O[nt][0] *= corr0; O[nt][1] *= corr0;
            O[nt][2] *= corr1; O[nt][3] *= corr1;
        }

        // ---- P -> A fragments (fp16 hi/lo) ----
        uint32_t aPh[4][4], aPl[4][4];
        #pragma unroll
        for (int kt = 0; kt < 4; ++kt){
            split_pair_h(Sa[2*kt][0],   Sa[2*kt][1],   aPh[kt][0], aPl[kt][0]);
            split_pair_h(Sa[2*kt][2],   Sa[2*kt][3],   aPh[kt][1], aPl[kt][1]);
            split_pair_h(Sa[2*kt+1][0], Sa[2*kt+1][1], aPh[kt][2], aPl[kt][2]);
            split_pair_h(Sa[2*kt+1][2], Sa[2*kt+1][3], aPh[kt][3], aPl[kt][3]);
        }

        // ---- O += P V (2-pass fp16, V via ldmatrix.trans) ----
        #pragma unroll
        for (int kt = 0; kt < 4; ++kt){
            #pragma unroll
            for (int dp = 0; dp < 8; ++dp){
                uint32_t bV[4];
                LDSM_X4_T(bV, Vst + vOff + kt*(16*AROWB) + dp*32);
                MMA_F16(O[2*dp],   aPh[kt], bV[0], bV[1]);
                MMA_F16(O[2*dp],   aPl[kt], bV[0], bV[1]);
                MMA_F16(O[2*dp+1], aPh[kt], bV[2], bV[3]);
                MMA_F16(O[2*dp+1], aPl[kt], bV[2], bV[3]);
            }
        }
    }

    // ---- epilogue: normalize, fp16 hi/lo to g_OH/g_OL ----
    const float inv0 = 1.0f / l0, inv1 = 1.0f / l1;
    const int s0 = qb*128 + wid*16 + (lane >> 2);
    const size_t ob = (size_t)b*S_*H_ + (size_t)h*HD_;
    #pragma unroll
    for (int nt = 0; nt < 16; ++nt){
        int d = nt*8 + (lane & 3)*2;
        uint32_t h2, l2;
        split_pair_h(O[nt][0]*inv0, O[nt][1]*inv0, h2, l2);
        size_t idx0 = ob + (size_t)s0*H_ + d;
        *(uint32_t*)(g_OH + idx0) = h2;
        *(uint32_t*)(g_OL + idx0) = l2;
        split_pair_h(O[nt][2]*inv1, O[nt][3]*inv1, h2, l2);
        size_t idx1 = ob + (size_t)(s0 + 8)*H_ + d;
        *(uint32_t*)(g_OH + idx1) = h2;
        *(uint32_t*)(g_OL + idx1) = l2;
    }
}

// ---------------- launch ----------------------------------------------------
extern "C" void kernel_launch(void* const* d_in, const int* in_sizes, int n_in,
                              void* d_out, int out_size)
{
    const float* hs = (const float*)d_in[0];
    const float* Wq = (const float*)d_in[1];
    const float* Wk = (const float*)d_in[2];
    const float* Wv = (const float*)d_in[3];
    const float* Wo = (const float*)d_in[4];
    float* out = (float*)d_out;

    rope_tables_kernel<<<(S_*64 + 255)/256, 256>>>();

    split_hs_kernel<<<(TOK*H_/4 + 255)/256, 256>>>(hs, TOK*H_);
    convert_h_kernel<<<(NH_*HD_*H_/4 + 255)/256, 256>>>(Wq, NH_*HD_*H_, 1);
    convert_h_kernel<<<(NKV_*HD_*H_/4 + 255)/256, 256>>>(Wk, NKV_*HD_*H_, 2);
    convert_h_kernel<<<(NKV_*HD_*H_/4 + 255)/256, 256>>>(Wv, NKV_*HD_*H_, 3);
    convert_h_kernel<<<(H_*H_/4 + 255)/256, 256>>>(Wo, H_*H_, 4);

    cudaFuncSetAttribute(gemm_hmma_kernel, cudaFuncAttributeMaxDynamicSharedMemorySize, GSMEM);

    gemm_hmma_kernel<<<dim3(32, 32), 256, GSMEM>>>(nullptr, 0, 0, 0, NH_);
    gemm_hmma_kernel<<<dim3(8,  32), 256, GSMEM>>>(nullptr, 0, 1, 1, NKV_);
    gemm_hmma_kernel<<<dim3(8,  32), 256, GSMEM>>>(nullptr, 0, 2, 2, NKV_);

    rope_convert_kernel<<<(B_*NH_*S_*64)/256,  256>>>(0, B_*NH_*S_);
    rope_convert_kernel<<<(B_*NKV_*S_*64)/256, 256>>>(1, B_*NKV_*S_);

    cudaFuncSetAttribute(attn_mma_kernel, cudaFuncAttributeMaxDynamicSharedMemorySize, ASMEM);
    attn_mma_kernel<<<dim3(S_/128, NH_, B_), 256, ASMEM>>>();

    gemm_hmma_kernel<<<dim3(32, 32), 256, GSMEM>>>(out, 1, 3, 3, 0);
}

// round 7
// speedup vs baseline: 4.2581x; 1.0132x over previous
#include <cuda_runtime.h>
#include <cuda_fp16.h>
#include <math.h>
#include <stdint.h>

#define B_   2
#define S_   2048
#define H_   4096
#define NH_  32
#define NKV_ 8
#define HD_  128
#define TOK  (B_*S_)        // 4096
#define QWN  (NH_*HD_*H_)   // 16777216
#define KWN  (NKV_*HD_*H_)  // 4194304

// ---------------- scratch (static device globals; no allocation) ----------
__device__ float g_cos[S_*64];
__device__ float g_sin[S_*64];

// fp16 operands
__device__ __half g_hsH[(size_t)TOK*H_], g_hsL[(size_t)TOK*H_];
__device__ __half g_Wq[(size_t)QWN];
__device__ __half g_Wk[(size_t)KWN];
__device__ __half g_Wv[(size_t)KWN];
__device__ __half g_Wo[(size_t)H_*H_];
__device__ __half g_OH[(size_t)TOK*H_], g_OL[(size_t)TOK*H_];

// attention operands (fp16; RoPE and scale pre-applied)
__device__ __half g_QbH[(size_t)B_*NH_*S_*HD_], g_QbL[(size_t)B_*NH_*S_*HD_];
__device__ __half g_Kb[(size_t)B_*NKV_*S_*HD_];
__device__ __half g_Vb[(size_t)B_*NKV_*S_*HD_];

// ---------------- helpers ----------------------------------------------------
__device__ __forceinline__ uint32_t smem_to_u32(const void* p){
    uint32_t a;
    asm("{ .reg .u64 t; cvta.to.shared.u64 t, %1; cvt.u32.u64 %0, t; }" : "=r"(a) : "l"(p));
    return a;
}
#define CP_ASYNC16(dst, src) \
    asm volatile("cp.async.cg.shared.global [%0], [%1], 16;" :: "r"(dst), "l"(src))
#define CP_COMMIT() asm volatile("cp.async.commit_group;" ::: "memory")
#define CP_WAIT1()  asm volatile("cp.async.wait_group 1;" ::: "memory")
#define CP_WAIT0()  asm volatile("cp.async.wait_group 0;" ::: "memory")

#define LDSM_X4(r, addr) \
    asm volatile("ldmatrix.sync.aligned.m8n8.x4.shared.b16 {%0,%1,%2,%3}, [%4];" \
        : "=r"((r)[0]),"=r"((r)[1]),"=r"((r)[2]),"=r"((r)[3]) : "r"(addr))
#define LDSM_X4_T(r, addr) \
    asm volatile("ldmatrix.sync.aligned.m8n8.x4.trans.shared.b16 {%0,%1,%2,%3}, [%4];" \
        : "=r"((r)[0]),"=r"((r)[1]),"=r"((r)[2]),"=r"((r)[3]) : "r"(addr))

#define MMA_F16(c, a, b0, b1) \
    asm volatile("mma.sync.aligned.m16n8k16.row.col.f32.f16.f16.f32 " \
        "{%0,%1,%2,%3},{%4,%5,%6,%7},{%8,%9},{%0,%1,%2,%3};" \
        : "+f"((c)[0]),"+f"((c)[1]),"+f"((c)[2]),"+f"((c)[3]) \
        : "r"((a)[0]),"r"((a)[1]),"r"((a)[2]),"r"((a)[3]), "r"(b0),"r"(b1))

__device__ __forceinline__ uint32_t f2h2(float x, float y){
    __half2 h = __floats2half2_rn(x, y);
    return *(uint32_t*)&h;
}
__device__ __forceinline__ void split_pair_h(float x, float y, uint32_t& h2, uint32_t& l2){
    h2 = f2h2(x, y);
    float2 f = __half22float2(*(__half2*)&h2);
    l2 = f2h2(x - f.x, y - f.y);
}
// fast e^x on FMA/ALU pipes. valid for x <= 0, clamps below -87.
__device__ __forceinline__ float fast_exp(float x){
    x = fmaxf(x, -87.0f);
    float y = x * 1.4426950408889634f;
    float r = __fadd_rn(y, 12582912.0f);
    float f = y - __fadd_rn(r, -12582912.0f);
    float p = 1.5403530e-4f;
    p = __fmaf_rn(p, f, 1.3333558e-3f);
    p = __fmaf_rn(p, f, 9.6181291e-3f);
    p = __fmaf_rn(p, f, 5.5504109e-2f);
    p = __fmaf_rn(p, f, 2.4022651e-1f);
    p = __fmaf_rn(p, f, 6.9314718e-1f);
    p = __fmaf_rn(p, f, 1.0f);
    int n = __float_as_int(r) - 0x4B400000;
    return __int_as_float(__float_as_int(p) + (n << 23));
}

// ---------------- rope tables ----------------------------------------------
__global__ void rope_tables_kernel(){
    int idx = blockIdx.x * blockDim.x + threadIdx.x;
    if (idx >= S_*64) return;
    int s = idx >> 6, j = idx & 63;
    double inv = pow(500000.0, -((double)j)/64.0);
    float ang = (float)s * (float)inv;
    g_cos[idx] = (float)cos((double)ang);
    g_sin[idx] = (float)sin((double)ang);
}

// ---------------- fp32 -> fp16 hi/lo split (hidden states), 8 floats/thread --
__global__ void split_hs_kernel(const float* __restrict__ src){
    size_t i = (((size_t)blockIdx.x << 8) + threadIdx.x) << 3;
    #pragma unroll
    for (int u = 0; u < 2; ++u){
        float4 v = *(const float4*)(src + i + u*4);
        uint32_t h0, l0, h1, l1;
        split_pair_h(v.x, v.y, h0, l0);
        split_pair_h(v.z, v.w, h1, l1);
        *(uint32_t*)(g_hsH + i + u*4)     = h0;
        *(uint32_t*)(g_hsH + i + u*4 + 2) = h1;
        *(uint32_t*)(g_hsL + i + u*4)     = l0;
        *(uint32_t*)(g_hsL + i + u*4 + 2) = l1;
    }
}

// ---------------- all weights fp32 -> fp16, one kernel, 8 floats/thread -----
__global__ void convert_weights_kernel(const float* __restrict__ Wq, const float* __restrict__ Wk,
                                       const float* __restrict__ Wv, const float* __restrict__ Wo){
    size_t i = (((size_t)blockIdx.x << 8) + threadIdx.x) << 3;
    const float* src; __half* dst; size_t off;
    if (i < QWN)              { src = Wq; dst = g_Wq; off = i; }
    else if (i < QWN + KWN)   { src = Wk; dst = g_Wk; off = i - QWN; }
    else if (i < QWN + 2*KWN) { src = Wv; dst = g_Wv; off = i - QWN - KWN; }
    else                      { src = Wo; dst = g_Wo; off = i - QWN - 2*KWN; }
    #pragma unroll
    for (int u = 0; u < 2; ++u){
        float4 v = *(const float4*)(src + off + u*4);
        *(uint32_t*)(dst + off + u*4)     = f2h2(v.x, v.y);
        *(uint32_t*)(dst + off + u*4 + 2) = f2h2(v.z, v.w);
    }
}

// ---------------- HMMA GEMM (fused QKV / O-proj), fp16 2-pass, 3-stage ------
// BM=128 BN=128 BK=32; 8 warps (4x2); 3-stage cp.async; 2 CTAs/SM.
#define BK_      32
#define ROWB     80
#define MATB     (128*ROWB)             // 10240
#define STGB     (3*MATB)               // 30720 (AH, AL, BH)
#define GSMEM    (3*STGB)               // 92160 (also covers 67584B epilogue staging)
#define KTILES   (H_/BK_)               // 128

__device__ __forceinline__ void hmma_load_stage(
    uint32_t sb, int s, const __half* AH, const __half* AL, const __half* BH,
    int M0, int N0, int kt, int tid)
{
    uint32_t base = sb + s*STGB;
    #pragma unroll
    for (int i = 0; i < 6; ++i){
        int c = tid + (i << 8);          // 0..1535
        int mat = c >> 9;                // 0=AH 1=AL 2=BH
        int cc = c & 511;
        int row = cc >> 2, ch = cc & 3;
        uint32_t soff = (uint32_t)mat*MATB + row*ROWB + (ch << 4);
        const __half* src = (mat == 0) ? AH : (mat == 1) ? AL : BH;
        int base_row = (mat == 2) ? N0 : M0;
        CP_ASYNC16(base + soff, src + (size_t)(base_row + row)*H_ + kt*BK_ + (ch << 3));
    }
}

// mode 0: fused QKV projections (blockIdx.x: 0-31 Q, 32-39 K, 40-47 V)
// mode 1: O projection -> Cout fp32
__global__ __launch_bounds__(256, 2)
void gemm_hmma_kernel(float* __restrict__ Cout, int mode)
{
    extern __shared__ char smem[];
    uint32_t sb = smem_to_u32(smem);
    const int tid = threadIdx.x;
    const int wid = tid >> 5, lane = tid & 31;
    const int wm = wid & 3, wn = wid >> 2;
    const int bx = blockIdx.x;
    const int M0 = blockIdx.y << 7;

    const __half *AH, *AL, *BH;
    int N0, dest, head = 0;
    if (mode == 1){
        AH = g_OH; AL = g_OL; BH = g_Wo;
        N0 = bx << 7; dest = 3;
    } else {
        AH = g_hsH; AL = g_hsL;
        if (bx < 32)      { BH = g_Wq; head = bx;      dest = 0; }
        else if (bx < 40) { BH = g_Wk; head = bx - 32; dest = 1; }
        else              { BH = g_Wv; head = bx - 40; dest = 2; }
        N0 = head << 7;
    }

    float acc[2][8][4];
    #pragma unroll
    for (int m = 0; m < 2; ++m)
        #pragma unroll
        for (int n = 0; n < 8; ++n)
            #pragma unroll
            for (int j = 0; j < 4; ++j) acc[m][n][j] = 0.f;

    hmma_load_stage(sb, 0, AH, AL, BH, M0, N0, 0, tid); CP_COMMIT();
    hmma_load_stage(sb, 1, AH, AL, BH, M0, N0, 1, tid); CP_COMMIT();

    const uint32_t aRow = (uint32_t)(wm*32 + (lane & 15));
    const uint32_t aColB = (uint32_t)(((lane >> 4) << 3) * 2);
    const uint32_t bRow = (uint32_t)(wn*64 + ((lane & 7) | ((lane & 16) >> 1)));
    const uint32_t bColB = (uint32_t)((((lane >> 3) & 1) << 3) * 2);

    #pragma unroll 1
    for (int kt = 0; kt < KTILES; ++kt){
        const int s = kt % 3;
        if (kt < KTILES - 1) { CP_WAIT1(); } else { CP_WAIT0(); }
        __syncthreads();
        if (kt + 2 < KTILES)
            hmma_load_stage(sb, (kt + 2) % 3, AH, AL, BH, M0, N0, kt + 2, tid);
        CP_COMMIT();

        const uint32_t stA = sb + s*STGB;
        const uint32_t stB = stA + 2*MATB;
        #pragma unroll
        for (int ks = 0; ks < 2; ++ks){
            const uint32_t kB = (uint32_t)(ks << 5);
            uint32_t aHr[2][4], aLr[2][4];
            #pragma unroll
            for (int mm = 0; mm < 2; ++mm){
                uint32_t off = (aRow + mm*16)*ROWB + kB + aColB;
                LDSM_X4(aHr[mm], stA + off);
                LDSM_X4(aLr[mm], stA + MATB + off);
            }
            #pragma unroll
            for (int g = 0; g < 4; ++g){
                uint32_t bH[4];
                uint32_t off = (bRow + g*16)*ROWB + kB + bColB;
                LDSM_X4(bH, stB + off);
                #pragma unroll
                for (int mm = 0; mm < 2; ++mm){
                    MMA_F16(acc[mm][2*g],   aHr[mm], bH[0], bH[1]);
                    MMA_F16(acc[mm][2*g],   aLr[mm], bH[0], bH[1]);
                    MMA_F16(acc[mm][2*g+1], aHr[mm], bH[2], bH[3]);
                    MMA_F16(acc[mm][2*g+1], aLr[mm], bH[2], bH[3]);
                }
            }
        }
    }

    // ---- epilogue ----
    const int rbase = wm*32 + (lane >> 2);
    const int cbase = wn*64 + (lane & 3)*2;
    if (dest == 3 || dest == 2){
        #pragma unroll
        for (int mm = 0; mm < 2; ++mm){
            #pragma unroll
            for (int half = 0; half < 2; ++half){
                int rl = rbase + mm*16 + half*8;
                int r = M0 + rl;
                #pragma unroll
                for (int nn = 0; nn < 8; ++nn){
                    float vx = acc[mm][nn][half*2];
                    float vy = acc[mm][nn][half*2 + 1];
                    if (dest == 3){
                        float2 v; v.x = vx; v.y = vy;
                        *(float2*)(Cout + (size_t)r*H_ + N0 + cbase + nn*8) = v;
                    } else {
                        int bb = r >> 11, ss = r & (S_ - 1);
                        size_t idx = (((size_t)bb*NKV_ + head)*S_ + ss)*HD_ + cbase + nn*8;
                        *(uint32_t*)(g_Vb + idx) = f2h2(vx, vy);
                    }
                }
            }
        }
    } else {
        // Q or K: stage tile in smem, apply RoPE (+scale for Q), write fp16
        __syncthreads();                 // pipeline smem reads done in all warps
        float* sm32 = (float*)smem;
        #pragma unroll
        for (int mm = 0; mm < 2; ++mm){
            #pragma unroll
            for (int half = 0; half < 2; ++half){
                int rl = rbase + mm*16 + half*8;
                #pragma unroll
                for (int nn = 0; nn < 8; ++nn){
                    float2 v;
                    v.x = acc[mm][nn][half*2];
                    v.y = acc[mm][nn][half*2 + 1];
                    *(float2*)(sm32 + rl*132 + cbase + nn*8) = v;
                }
            }
        }
        __syncthreads();
        const float qsc = 0.08838834764831845f;
        #pragma unroll 4
        for (int i = tid; i < 128*64; i += 256){
            int r = i >> 6, j = i & 63;
            int token = M0 + r;
            int bb = token >> 11, ss = token & (S_ - 1);
            float c  = g_cos[(ss << 6) + j];
            float sn = g_sin[(ss << 6) + j];
            float x1 = sm32[r*132 + j], x2 = sm32[r*132 + j + 64];
            float y1 = x1*c - x2*sn;
            float y2 = x2*c + x1*sn;
            if (dest == 0){
                y1 *= qsc; y2 *= qsc;
                size_t base = (((size_t)bb*NH_ + head)*S_ + ss)*HD_;
                __half h1 = __float2half_rn(y1), h2v = __float2half_rn(y2);
                g_QbH[base + j]      = h1;
                g_QbH[base + j + 64] = h2v;
                g_QbL[base + j]      = __float2half_rn(y1 - __half2float(h1));
                g_QbL[base + j + 64] = __float2half_rn(y2 - __half2float(h2v));
            } else {
                size_t base = (((size_t)bb*NKV_ + head)*S_ + ss)*HD_;
                g_Kb[base + j]      = __float2half_rn(y1);
                g_Kb[base + j + 64] = __float2half_rn(y2);
            }
        }
    }
}

// ---------------- HMMA flash attention (fp16 2-pass, 3-stage K/V) -----------
#define AROWB 272
#define AQMAT (128*AROWB)               // 34816
#define AKMAT (64*AROWB)                // 17408
#define ASTGB (2*AKMAT)                 // K + V = 34816
#define ASMEM (2*AQMAT + 3*ASTGB)       // 174080
#define NKB   (S_/64)                   // 32

__device__ __forceinline__ void attn_load_kv(
    uint32_t st, const __half* Kg, const __half* Vg, int key0, int tid)
{
    #pragma unroll
    for (int i = 0; i < 8; ++i){
        int c = tid + (i << 8);          // 0..2047
        int mat = c >> 10;               // 0=K 1=V
        int cc = c & 1023;
        int row = cc >> 4, ch = cc & 15;
        uint32_t dst = st + (uint32_t)mat*AKMAT + row*AROWB + (ch << 4);
        const __half* src = mat ? Vg : Kg;
        CP_ASYNC16(dst, src + (size_t)(key0 + row)*HD_ + (ch << 3));
    }
}

__global__ __launch_bounds__(256, 1)
void attn_mma_kernel(){
    extern __shared__ char smem[];
    uint32_t sb = smem_to_u32(smem);
    const int tid = threadIdx.x;
    const int wid = tid >> 5, lane = tid & 31;
    const int qb = blockIdx.x, h = blockIdx.y, b = blockIdx.z;
    const int g = h >> 2;

    const __half* QHg = g_QbH + (((size_t)b*NH_ + h)*S_ + (size_t)qb*128)*HD_;
    const __half* QLg = g_QbL + (((size_t)b*NH_ + h)*S_ + (size_t)qb*128)*HD_;
    const __half* Kg  = g_Kb + ((size_t)b*NKV_ + g)*S_*HD_;
    const __half* Vg  = g_Vb + ((size_t)b*NKV_ + g)*S_*HD_;

    const uint32_t QH0 = sb, QL0 = sb + AQMAT;
    const uint32_t KVB = sb + 2*AQMAT;

    #pragma unroll
    for (int i = 0; i < 16; ++i){
        int c = tid + (i << 8);
        int mat = c >> 11;
        int cc = c & 2047;
        int row = cc >> 4, ch = cc & 15;
        uint32_t dst = (mat ? QL0 : QH0) + row*AROWB + (ch << 4);
        const __half* src = mat ? QLg : QHg;
        CP_ASYNC16(dst, src + (size_t)row*HD_ + (ch << 3));
    }
    attn_load_kv(KVB, Kg, Vg, 0, tid);
    CP_COMMIT();
    attn_load_kv(KVB + ASTGB, Kg, Vg, 64, tid);
    CP_COMMIT();

    float m0 = -1e30f, m1 = -1e30f, l0 = 0.f, l1 = 0.f;
    float O[16][4];
    #pragma unroll
    for (int nt = 0; nt < 16; ++nt)
        #pragma unroll
        for (int j = 0; j < 4; ++j) O[nt][j] = 0.f;

    const uint32_t aOff  = (uint32_t)(wid*16 + (lane & 15))*AROWB + ((lane >> 4) << 4);
    const uint32_t bOffK = (uint32_t)((lane & 7) | ((lane & 16) >> 1))*AROWB + (((lane >> 3) & 1) << 4);
    const uint32_t vOff  = (uint32_t)((lane & 7) + (lane & 8))*AROWB + ((lane >> 4) << 4);

    #pragma unroll 1
    for (int kb = 0; kb < NKB; ++kb){
        const int s = kb % 3;
        const uint32_t Kst = KVB + s*ASTGB;
        const uint32_t Vst = Kst + AKMAT;

        if (kb < NKB - 1) { CP_WAIT1(); } else { CP_WAIT0(); }
        __syncthreads();
        if (kb + 2 < NKB)
            attn_load_kv(KVB + ((kb + 2) % 3)*ASTGB, Kg, Vg, (kb+2)*64, tid);
        CP_COMMIT();

        // ---- S = Q K^T (2-pass fp16) ----
        float Sa[8][4];
        #pragma unroll
        for (int nt = 0; nt < 8; ++nt)
            #pragma unroll
            for (int j = 0; j < 4; ++j) Sa[nt][j] = 0.f;

        #pragma unroll
        for (int ks = 0; ks < 8; ++ks){
            uint32_t aH[4], aL[4];
            LDSM_X4(aH, QH0 + aOff + ks*32);
            LDSM_X4(aL, QL0 + aOff + ks*32);
            #pragma unroll
            for (int gi = 0; gi < 4; ++gi){
                uint32_t bK[4];
                LDSM_X4(bK, Kst + bOffK + gi*(16*AROWB) + ks*32);
                MMA_F16(Sa[2*gi],   aH, bK[0], bK[1]);
                MMA_F16(Sa[2*gi],   aL, bK[0], bK[1]);
                MMA_F16(Sa[2*gi+1], aH, bK[2], bK[3]);
                MMA_F16(Sa[2*gi+1], aL, bK[2], bK[3]);
            }
        }

        // ---- online softmax ----
        float mb0 = -1e30f, mb1 = -1e30f;
        #pragma unroll
        for (int nt = 0; nt < 8; ++nt){
            mb0 = fmaxf(mb0, fmaxf(Sa[nt][0], Sa[nt][1]));
            mb1 = fmaxf(mb1, fmaxf(Sa[nt][2], Sa[nt][3]));
        }
        mb0 = fmaxf(mb0, __shfl_xor_sync(0xffffffffu, mb0, 1));
        mb0 = fmaxf(mb0, __shfl_xor_sync(0xffffffffu, mb0, 2));
        mb1 = fmaxf(mb1, __shfl_xor_sync(0xffffffffu, mb1, 1));
        mb1 = fmaxf(mb1, __shfl_xor_sync(0xffffffffu, mb1, 2));
        float m0n = fmaxf(m0, mb0), m1n = fmaxf(m1, mb1);
        float corr0 = fast_exp(m0 - m0n), corr1 = fast_exp(m1 - m1n);
        m0 = m0n; m1 = m1n;

        float ls0 = 0.f, ls1 = 0.f;
        #pragma unroll
        for (int nt = 0; nt < 8; ++nt){
            Sa[nt][0] = fast_exp(Sa[nt][0] - m0);
            Sa[nt][1] = fast_exp(Sa[nt][1] - m0);
            Sa[nt][2] = fast_exp(Sa[nt][2] - m1);
            Sa[nt][3] = fast_exp(Sa[nt][3] - m1);
            ls0 += Sa[nt][0] + Sa[nt][1];
            ls1 += Sa[nt][2] + Sa[nt][3];
        }
        ls0 += __shfl_xor_sync(0xffffffffu, ls0, 1);
        ls0 += __shfl_xor_sync(0xffffffffu, ls0, 2);
        ls1 += __shfl_xor_sync(0xffffffffu, ls1, 1);
        ls1 += __shfl_xor_sync(0xffffffffu, ls1, 2);
        l0 = l0*corr0 + ls0;
        l1 = l1*corr1 + ls1;

        #pragma unroll
        for (int nt = 0; nt < 16; ++nt){
            O[nt][0] *= corr0; O[nt][1] *= corr0;
            O[nt][2] *= corr1; O[nt][3] *= corr1;
        }

        // ---- P -> A fragments (fp16 hi/lo) ----
        uint32_t aPh[4][4], aPl[4][4];
        #pragma unroll
        for (int kt = 0; kt < 4; ++kt){
            split_pair_h(Sa[2*kt][0],   Sa[2*kt][1],   aPh[kt][0], aPl[kt][0]);
            split_pair_h(Sa[2*kt][2],   Sa[2*kt][3],   aPh[kt][1], aPl[kt][1]);
            split_pair_h(Sa[2*kt+1][0], Sa[2*kt+1][1], aPh[kt][2], aPl[kt][2]);
            split_pair_h(Sa[2*kt+1][2], Sa[2*kt+1][3], aPh[kt][3], aPl[kt][3]);
        }

        // ---- O += P V (2-pass fp16, V via ldmatrix.trans) ----
        #pragma unroll
        for (int kt = 0; kt < 4; ++kt){
            #pragma unroll
            for (int dp = 0; dp < 8; ++dp){
                uint32_t bV[4];
                LDSM_X4_T(bV, Vst + vOff + kt*(16*AROWB) + dp*32);
                MMA_F16(O[2*dp],   aPh[kt], bV[0], bV[1]);
                MMA_F16(O[2*dp],   aPl[kt], bV[0], bV[1]);
                MMA_F16(O[2*dp+1], aPh[kt], bV[2], bV[3]);
                MMA_F16(O[2*dp+1], aPl[kt], bV[2], bV[3]);
            }
        }
    }

    // ---- epilogue: normalize, fp16 hi/lo to g_OH/g_OL ----
    const float inv0 = 1.0f / l0, inv1 = 1.0f / l1;
    const int s0 = qb*128 + wid*16 + (lane >> 2);
    const size_t ob = (size_t)b*S_*H_ + (size_t)h*HD_;
    #pragma unroll
    for (int nt = 0; nt < 16; ++nt){
        int d = nt*8 + (lane & 3)*2;
        uint32_t h2, l2;
        split_pair_h(O[nt][0]*inv0, O[nt][1]*inv0, h2, l2);
        size_t idx0 = ob + (size_t)s0*H_ + d;
        *(uint32_t*)(g_OH + idx0) = h2;
        *(uint32_t*)(g_OL + idx0) = l2;
        split_pair_h(O[nt][2]*inv1, O[nt][3]*inv1, h2, l2);
        size_t idx1 = ob + (size_t)(s0 + 8)*H_ + d;
        *(uint32_t*)(g_OH + idx1) = h2;
        *(uint32_t*)(g_OL + idx1) = l2;
    }
}

// ---------------- launch ----------------------------------------------------
extern "C" void kernel_launch(void* const* d_in, const int* in_sizes, int n_in,
                              void* d_out, int out_size)
{
    const float* hs = (const float*)d_in[0];
    const float* Wq = (const float*)d_in[1];
    const float* Wk = (const float*)d_in[2];
    const float* Wv = (const float*)d_in[3];
    const float* Wo = (const float*)d_in[4];
    float* out = (float*)d_out;

    rope_tables_kernel<<<(S_*64 + 255)/256, 256>>>();
    split_hs_kernel<<<TOK*H_/(8*256), 256>>>(hs);
    convert_weights_kernel<<<(QWN + 2*KWN + H_*H_)/(8*256), 256>>>(Wq, Wk, Wv, Wo);

    cudaFuncSetAttribute(gemm_hmma_kernel, cudaFuncAttributeMaxDynamicSharedMemorySize, GSMEM);
    cudaFuncSetAttribute(attn_mma_kernel, cudaFuncAttributeMaxDynamicSharedMemorySize, ASMEM);

    // fused Q/K/V projections with RoPE + fp16 conversion in epilogue
    gemm_hmma_kernel<<<dim3(48, 32), 256, GSMEM>>>(nullptr, 0);

    // flash attention
    attn_mma_kernel<<<dim3(S_/128, NH_, B_), 256, ASMEM>>>();

    // output projection -> d_out
    gemm_hmma_kernel<<<dim3(32, 32), 256, GSMEM>>>(out, 1);
}